// round 10
// baseline (speedup 1.0000x reference)
#include <cuda_runtime.h>
#include <cuda_bf16.h>
#include <math.h>
#include <stdint.h>

#define BSZ 8
#define CH 192
#define HWP 4096
#define MASKN 16

typedef __nv_bfloat16 bf16;

// ---- scratch (static device globals) ----
__device__ bf16 g_b0[BSZ * CH * HWP];    // dyn-conv output
__device__ bf16 g_b1[BSZ * CH * HWP];    // x
__device__ bf16 g_b2[BSZ * CH * HWP];    // y0 (channel-pair interleaved!)
__device__ bf16 g_b3[BSZ * CH * HWP];    // y1
__device__ bf16 g_w0b[CH * CH];
__device__ bf16 g_w1b[CH * CH];
__device__ bf16 g_wsxb[CH * CH];         // x-half of ws0
__device__ bf16 g_wob[CH * CH];
__device__ bf16 g_wrb[9 * CH * CH];      // reordered ws1: [r][co][ci]
__device__ float g_T[BSZ * MASKN * CH];
__device__ float g_mean[BSZ * CH];
__device__ float g_gate[BSZ * CH];

// ---- bf16 mma m16n8k16 (row.col), fp32 accumulate ----
__device__ __forceinline__ void mma_bf16(float* c, const uint32_t* a, uint32_t b0, uint32_t b1)
{
    asm("mma.sync.aligned.m16n8k16.row.col.f32.bf16.bf16.f32 "
        "{%0,%1,%2,%3}, {%4,%5,%6,%7}, {%8,%9}, {%0,%1,%2,%3};\n"
        : "+f"(c[0]), "+f"(c[1]), "+f"(c[2]), "+f"(c[3])
        : "r"(a[0]), "r"(a[1]), "r"(a[2]), "r"(a[3]), "r"(b0), "r"(b1));
}

#define LDMX2T(b0, b1, addr) \
    asm volatile("ldmatrix.sync.aligned.m8n8.x2.trans.shared.b16 {%0,%1}, [%2];\n" \
                 : "=r"(b0), "=r"(b1) : "r"(addr))

#define LDMX4(r0, r1, r2, r3, addr) \
    asm volatile("ldmatrix.sync.aligned.m8n8.x4.shared.b16 {%0,%1,%2,%3}, [%4];\n" \
                 : "=r"(r0), "=r"(r1), "=r"(r2), "=r"(r3) : "r"(addr))

#define CP16(dst, src) \
    asm volatile("cp.async.cg.shared.global [%0], [%1], 16;\n" :: "r"(dst), "l"(src))
#define CP_COMMIT() asm volatile("cp.async.commit_group;\n")
#define CP_WAIT0()  asm volatile("cp.async.wait_group 0;\n")

// ============================================================
// Fused chain: v = lrelu(W0@in), x = W1@v, y0 = lrelu(Wsx@x + T + bs0)
// Activation tile (128 px, all 192 ch) resident in SMEM (ping-pong).
// 9 (phase, m-chunk) steps in ONE pipeline with double-buffered A
// panels: every panel load hides under the previous step's compute.
// 256 threads = 8 warps (2m x 4n), warp tile 32x32.
// grid (32, 1, 8) = 256 CTAs -> all 148 SMs busy in wave 1.
// ============================================================
#define BST 136            // B row stride in halves (272B; 68w % 32 = 4 spread)
#define BBUF (CH * BST)    // 26112 halves per activation buffer
#define AST 200            // A row stride in halves (400B)
#define APAN (64 * AST)    // 12800 halves per panel

__global__ __launch_bounds__(256) void chain3_tc(
    const float* __restrict__ input,
    const bf16* __restrict__ W0, const bf16* __restrict__ W1,
    const bf16* __restrict__ Wsx,
    const float* __restrict__ bias0, const float* __restrict__ bias1,
    const float* __restrict__ bias2,
    const int* __restrict__ mask, const float* __restrict__ Tt,
    bf16* __restrict__ Xout, bf16* __restrict__ Y0i)
{
    extern __shared__ __align__(16) bf16 sm[];
    bf16* Bbuf0 = sm;
    bf16* Bbuf1 = sm + BBUF;
    bf16* As    = sm + 2 * BBUF;     // [2][64][AST]

    const int b   = blockIdx.z;
    const int n0  = blockIdx.x * 128;
    const int tid = threadIdx.x;
    const int lane = tid & 31;
    const int warp = tid >> 5;     // 0..7
    const int wm = warp >> 2;      // 0..1
    const int wn = warp & 3;       // 0..3
    const int tq = lane & 3;
    const int gq = lane >> 2;
    const int lg = lane >> 3;
    const int arow = (lg & 1) * 8 + (lane & 7);
    const int akoff = (lg >> 1) * 8;

    // ---- stage input tile fp32 -> bf16 into Bbuf0 ----
    const float* inb = input + (size_t)b * CH * HWP;
    for (int idx = tid; idx < CH * 64; idx += 256) {
        int ch = idx >> 6, pu = idx & 63;
        float2 v = *(const float2*)(inb + (size_t)ch * HWP + n0 + 2 * pu);
        __nv_bfloat162 o;
        o.x = __float2bfloat16(v.x);
        o.y = __float2bfloat16(v.y);
        *(__nv_bfloat162*)(Bbuf0 + ch * BST + 2 * pu) = o;
    }

    uint32_t s_as = (uint32_t)__cvta_generic_to_shared(As);

    auto issue = [&](int p, int st) {
        int ph = p / 3, mc = p - ph * 3;
        const bf16* W = (ph == 0) ? W0 : (ph == 1 ? W1 : Wsx);
#pragma unroll
        for (int t = 0; t < 6; t++) {
            int idx = tid + t * 256;          // 1536 chunks exactly
            int i = idx / 24, c8 = (idx % 24) * 8;
            CP16(s_as + (uint32_t)(st * APAN + i * AST + c8) * 2,
                 W + (size_t)(mc * 64 + i) * CH + c8);
        }
    };

    issue(0, 0);
    CP_COMMIT();

#pragma unroll 1
    for (int p = 0; p < 9; p++) {
        const int ph = p / 3;
        const int m0 = (p - ph * 3) * 64;
        const float* bias = (ph == 0) ? bias0 : (ph == 1 ? bias1 : bias2);
        bf16* Bsrc = (ph == 1) ? Bbuf1 : Bbuf0;
        bf16* Bdst = (ph == 0) ? Bbuf1 : Bbuf0;   // unused for ph==2
        uint32_t s_bsrc = (uint32_t)__cvta_generic_to_shared(Bsrc);
        uint32_t sAc = s_as + (p & 1) * APAN * 2;

        CP_WAIT0();
        __syncthreads();          // panel p ready; prior compute/staging done
        if (p < 8) { issue(p + 1, (p + 1) & 1); CP_COMMIT(); }

        float c[2][4][4];
#pragma unroll
        for (int i = 0; i < 2; i++)
#pragma unroll
            for (int j = 0; j < 4; j++)
#pragma unroll
                for (int q = 0; q < 4; q++) c[i][j][q] = 0.f;

#pragma unroll
        for (int kt = 0; kt < CH; kt += 16) {
            uint32_t a[2][4];
#pragma unroll
            for (int mt = 0; mt < 2; mt++) {
                uint32_t aadr = sAc
                    + (uint32_t)((wm * 32 + mt * 16 + arow) * AST + kt + akoff) * 2;
                LDMX4(a[mt][0], a[mt][1], a[mt][2], a[mt][3], aadr);
            }
            uint32_t badr = s_bsrc
                + (uint32_t)((kt + (lane & 15)) * BST + wn * 32) * 2;
#pragma unroll
            for (int nt = 0; nt < 4; nt++) {
                uint32_t bf0, bf1;
                LDMX2T(bf0, bf1, badr + nt * 16);
                mma_bf16(c[0][nt], a[0], bf0, bf1);
                mma_bf16(c[1][nt], a[1], bf0, bf1);
            }
        }

        // epilogue
#pragma unroll
        for (int mt = 0; mt < 2; mt++) {
#pragma unroll
            for (int half = 0; half < 2; half++) {
                int co = m0 + wm * 32 + mt * 16 + gq + half * 8;
                float bi = bias[co];
#pragma unroll
                for (int nt = 0; nt < 4; nt++) {
                    int ploc = wn * 32 + nt * 8 + tq * 2;
                    float v0 = c[mt][nt][half * 2 + 0] + bi;
                    float v1 = c[mt][nt][half * 2 + 1] + bi;
                    if (ph == 2) {
                        int pp = n0 + ploc;
                        int mk0 = mask[b * HWP + pp];
                        int mk1 = mask[b * HWP + pp + 1];
                        v0 += Tt[(b * MASKN + mk0) * CH + co];
                        v1 += Tt[(b * MASKN + mk1) * CH + co];
                    }
                    if (ph != 1) {
                        v0 = v0 > 0.f ? v0 : 0.1f * v0;
                        v1 = v1 > 0.f ? v1 : 0.1f * v1;
                    }
                    if (ph < 2) {
                        __nv_bfloat162 o;
                        o.x = __float2bfloat16(v0);
                        o.y = __float2bfloat16(v1);
                        *(__nv_bfloat162*)(Bdst + co * BST + ploc) = o;
                    }
                    if (ph == 1) {
                        __nv_bfloat162 o;
                        o.x = __float2bfloat16(v0);
                        o.y = __float2bfloat16(v1);
                        *(__nv_bfloat162*)(Xout + ((size_t)b * CH + co) * HWP + n0 + ploc) = o;
                    }
                    if (ph == 2) {
                        size_t w = ((size_t)b * (CH / 2) + (co >> 1)) * HWP + n0 + ploc;
                        bf16* dst = Y0i + w * 2 + (co & 1);
                        dst[0] = __float2bfloat16(v0);
                        dst[2] = __float2bfloat16(v1);
                    }
                }
            }
        }
    }
}

// ============================================================
// FINAL 1x1 conv GEMM (gate folded into A; fp32 out + residual).
// ============================================================
__global__ __launch_bounds__(256) void gemm_final_tc(
    const bf16* __restrict__ X, const bf16* __restrict__ Wb,
    const float* __restrict__ bias, float* __restrict__ Y,
    const float* __restrict__ gate, const float* __restrict__ resid)
{
    __shared__ __align__(16) bf16 As[2][64][24];
    __shared__ __align__(16) bf16 Bs[2][16][264];
    __shared__ float sgate[CH];

    const int b   = blockIdx.z;
    const int m0  = blockIdx.y * 64;
    const int n0  = blockIdx.x * 256;
    const int tid = threadIdx.x;
    const int lane = tid & 31;
    const int warp = tid >> 5;
    const int wm = warp >> 2;
    const int wn = warp & 3;
    const int tq = lane & 3;
    const int gq = lane >> 2;
    const int lg = lane >> 3;
    const int arow = (lg & 1) * 8 + (lane & 7);
    const int akoff = (lg >> 1) * 8;

    const bf16* Xb = X + (size_t)b * CH * HWP;

    if (tid < CH) sgate[tid] = gate[b * CH + tid];
    __syncthreads();

    uint32_t s_as = (uint32_t)__cvta_generic_to_shared(&As[0][0][0]);
    uint32_t s_bs = (uint32_t)__cvta_generic_to_shared(&Bs[0][0][0]);

    float c[2][8][4];
#pragma unroll
    for (int i = 0; i < 2; i++)
#pragma unroll
        for (int j = 0; j < 8; j++)
#pragma unroll
            for (int q = 0; q < 4; q++) c[i][j][q] = 0.f;

    auto issue = [&](int kt, int st) {
        if (tid < 128) {
            int co = tid >> 1, h8 = (tid & 1) * 8;
            const bf16* src = Wb + (size_t)(m0 + co) * CH + kt + h8;
            bf16 tmp[8];
            *(uint4*)tmp = *(const uint4*)src;
            bf16 dst8[8];
#pragma unroll
            for (int i = 0; i < 8; i++)
                dst8[i] = __float2bfloat16(__bfloat162float(tmp[i]) * sgate[kt + h8 + i]);
            *(uint4*)&As[st][co][h8] = *(uint4*)dst8;
        }
#pragma unroll
        for (int t = 0; t < 2; t++) {
            int idx = tid + t * 256;
            int k = idx >> 5, q = idx & 31;
            CP16(s_bs + (uint32_t)(st * 4224 + k * 264 + q * 8) * 2,
                 Xb + (size_t)(kt + k) * HWP + n0 + q * 8);
        }
    };

    issue(0, 0);
    CP_COMMIT();

    for (int step = 0; step < 12; step++) {
        CP_WAIT0();
        __syncthreads();
        if (step < 11) { issue((step + 1) * 16, (step + 1) & 1); CP_COMMIT(); }

        uint32_t sAc = s_as + (step & 1) * 1536 * 2;
        uint32_t sBc = s_bs + (step & 1) * 4224 * 2;

        uint32_t a[2][4];
#pragma unroll
        for (int mt = 0; mt < 2; mt++) {
            uint32_t aadr = sAc + (uint32_t)((wm * 32 + mt * 16 + arow) * 24 + akoff) * 2;
            LDMX4(a[mt][0], a[mt][1], a[mt][2], a[mt][3], aadr);
        }
        uint32_t badr = sBc + (uint32_t)((lane & 15) * 264 + wn * 64) * 2;
#pragma unroll
        for (int nt = 0; nt < 8; nt++) {
            uint32_t b0, b1;
            LDMX2T(b0, b1, badr + nt * 16);
            mma_bf16(c[0][nt], a[0], b0, b1);
            mma_bf16(c[1][nt], a[1], b0, b1);
        }
    }

#pragma unroll
    for (int mt = 0; mt < 2; mt++) {
#pragma unroll
        for (int half = 0; half < 2; half++) {
            int co = m0 + wm * 32 + mt * 16 + gq + half * 8;
            float bi = bias[co];
#pragma unroll
            for (int nt = 0; nt < 8; nt++) {
                int p = n0 + wn * 64 + nt * 8 + tq * 2;
                size_t off = ((size_t)b * CH + co) * HWP + p;
                float v0 = c[mt][nt][half * 2 + 0] + bi + resid[off];
                float v1 = c[mt][nt][half * 2 + 1] + bi + resid[off + 1];
                *(float2*)(Y + off) = make_float2(v0, v1);
            }
        }
    }
}

// ============================================================
// 3x3 conv, bf16 TC, channel-pair interleaved B, ldmatrix A.
// 128 threads = 4 warps, warp tile 64x64, 2 CTAs/SM. (unchanged R9)
// ============================================================
#define PSTW 440
#define PSTAGEW (8 * PSTW)
__global__ __launch_bounds__(128, 2) void conv3x3_tc(
    const bf16* __restrict__ Y0i, const bf16* __restrict__ Wr,
    const float* __restrict__ bias, bf16* __restrict__ Y)
{
    extern __shared__ __align__(16) bf16 smem[];
    bf16* Asb = smem;
    uint32_t* Psb = (uint32_t*)(smem + 2 * 13824);

    const int b    = blockIdx.z;
    const int m0   = blockIdx.y * 64;
    const int tile = blockIdx.x;
    const int row0 = tile * 4;
    const int n0   = tile * 256;
    const int tid  = threadIdx.x;
    const int lane = tid & 31;
    const int wn   = tid >> 5;
    const int tq = lane & 3;
    const int gq = lane >> 2;
    const int lg = lane >> 3;
    const int arow = (lg & 1) * 8 + (lane & 7);
    const int akoff = (lg >> 1) * 8;

    const uint32_t* Xw = (const uint32_t*)Y0i + (size_t)b * (CH / 2) * HWP;

    for (int i = tid; i < 2 * PSTAGEW; i += 128) Psb[i] = 0u;
    __syncthreads();

    uint32_t s_as = (uint32_t)__cvta_generic_to_shared(Asb);
    uint32_t s_ps = (uint32_t)__cvta_generic_to_shared(Psb);

    float c[4][8][4];
#pragma unroll
    for (int i = 0; i < 4; i++)
#pragma unroll
        for (int j = 0; j < 8; j++)
#pragma unroll
            for (int q = 0; q < 4; q++) c[i][j][q] = 0.f;

    auto issue = [&](int kt, int st) {
        uint32_t ab = s_as + st * (13824 * 2);
#pragma unroll
        for (int t = 0; t < 9; t++) {
            int idx = tid + t * 128;
            int r = idx >> 7;
            int rem = idx & 127;
            int co = rem >> 1, h8 = (rem & 1) * 8;
            CP16(ab + (uint32_t)((r * 64 + co) * 24 + h8) * 2,
                 Wr + ((size_t)r * CH + m0 + co) * CH + kt + h8);
        }
        uint32_t pb = s_ps + st * (PSTAGEW * 4);
        const int cp0 = kt >> 1;
#pragma unroll
        for (int t = 0; t < 6; t++) {
            int idx = tid + t * 128;
            int m = idx / 96;
            int rem = idx - m * 96;
            int rr = rem >> 4;
            int q  = rem & 15;
            int hh = row0 + rr - 1;
            if (hh >= 0 && hh < 64) {
                CP16(pb + (uint32_t)(m * PSTW + rr * 72 + 8 + q * 4) * 4,
                     Xw + (size_t)(cp0 + m) * HWP + hh * 64 + q * 4);
            }
        }
    };

    issue(0, 0);
    CP_COMMIT();

    for (int step = 0; step < 12; step++) {
        CP_WAIT0();
        __syncthreads();
        if (step < 11) { issue((step + 1) * 16, (step + 1) & 1); CP_COMMIT(); }

        uint32_t sAc = s_as + (step & 1) * (13824 * 2);
        const uint32_t* Pw = Psb + (step & 1) * PSTAGEW;

#pragma unroll 1
        for (int r = 0; r < 9; r++) {
            const int di = r / 3, dj = r - (r / 3) * 3;

            uint32_t a[4][4];
#pragma unroll
            for (int mt = 0; mt < 4; mt++) {
                uint32_t aadr = sAc
                    + (uint32_t)((r * 64 + mt * 16 + arow) * 24 + akoff) * 2;
                LDMX4(a[mt][0], a[mt][1], a[mt][2], a[mt][3], aadr);
            }
            const uint32_t* pr0 = Pw + tq * PSTW + (wn + di) * 72 + gq + dj + 7;
            const uint32_t* pr1 = pr0 + 4 * PSTW;
#pragma unroll
            for (int nt = 0; nt < 8; nt++) {
                uint32_t b0 = pr0[nt * 8];
                uint32_t b1 = pr1[nt * 8];
#pragma unroll
                for (int mt = 0; mt < 4; mt++)
                    mma_bf16(c[mt][nt], a[mt], b0, b1);
            }
        }
    }

#pragma unroll
    for (int mt = 0; mt < 4; mt++) {
#pragma unroll
        for (int half = 0; half < 2; half++) {
            int co = m0 + mt * 16 + gq + half * 8;
            float bi = bias[co];
#pragma unroll
            for (int nt = 0; nt < 8; nt++) {
                int p = n0 + wn * 64 + nt * 8 + tq * 2;
                float v0 = c[mt][nt][half * 2 + 0] + bi;
                float v1 = c[mt][nt][half * 2 + 1] + bi;
                v0 = v0 > 0.f ? v0 : 0.1f * v0;
                v1 = v1 > 0.f ? v1 : 0.1f * v1;
                __nv_bfloat162 o;
                o.x = __float2bfloat16(v0);
                o.y = __float2bfloat16(v1);
                *(__nv_bfloat162*)&Y[((size_t)b * CH + co) * HWP + p] = o;
            }
        }
    }
}

// ============================================================
// prep: convert weights to bf16 (+ reorder ws1 -> [r][co][ci])
// ============================================================
__global__ void prep_weights(
    const float* __restrict__ w0, const float* __restrict__ w1,
    const float* __restrict__ ws0, const float* __restrict__ ws1,
    const float* __restrict__ wo,
    bf16* __restrict__ w0b, bf16* __restrict__ w1b,
    bf16* __restrict__ wsxb, bf16* __restrict__ wob,
    bf16* __restrict__ wrb)
{
    const int S = CH * CH;
    int idx = blockIdx.x * 256 + threadIdx.x;
    if (idx < S) {
        w0b[idx] = __float2bfloat16(w0[idx]);
    } else if (idx < 2 * S) {
        int i = idx - S;
        w1b[i] = __float2bfloat16(w1[i]);
    } else if (idx < 3 * S) {
        int i = idx - 2 * S;
        int co = i / CH, ci = i % CH;
        wsxb[i] = __float2bfloat16(ws0[(size_t)co * (2 * CH) + ci]);
    } else if (idx < 4 * S) {
        int i = idx - 3 * S;
        wob[i] = __float2bfloat16(wo[i]);
    } else if (idx < 4 * S + 9 * S) {
        int i = idx - 4 * S;
        int ci = i % CH;
        int co = (i / CH) % CH;
        int r  = i / S;
        wrb[i] = __float2bfloat16(ws1[((size_t)co * CH + ci) * 9 + r]);
    }
}

// ============================================================
// T[b,m,co] = sum_ci ws0[co, 192+ci] * list_center[b,m,ci]
// ============================================================
__global__ __launch_bounds__(256) void tgen_kernel(
    const float* __restrict__ lc, const float* __restrict__ ws0,
    float* __restrict__ T)
{
    __shared__ float cvec[CH];
    const int bm = blockIdx.x;
    const int cg = blockIdx.y;
    const int tid = threadIdx.x;
    if (tid < CH) cvec[tid] = lc[(size_t)bm * CH + tid];
    __syncthreads();
    const int warp = tid >> 5, lane = tid & 31;
    const int co0 = cg * 32 + warp * 4;
#pragma unroll
    for (int q = 0; q < 4; q++) {
        const float* w = ws0 + (size_t)(co0 + q) * (2 * CH) + CH;
        float s = 0.f;
#pragma unroll
        for (int j = lane; j < CH; j += 32) s = fmaf(w[j], cvec[j], s);
#pragma unroll
        for (int o = 16; o; o >>= 1) s += __shfl_xor_sync(0xffffffffu, s, o);
        if (lane == 0) T[bm * CH + co0 + q] = s;
    }
}

// ============================================================
// Fused depthwise-3x3 (k_sp) + dynamic conv + mean reduce. bf16 I/O.
// ============================================================
__global__ __launch_bounds__(256) void dyn_kernel(
    const bf16* __restrict__ Y1, const bf16* __restrict__ Xf,
    const float* __restrict__ ws2, const float* __restrict__ bs2,
    bf16* __restrict__ Out, float* __restrict__ Mean)
{
    __shared__ float sy[66 * 66];
    __shared__ float sx[66 * 66];
    __shared__ float taps[81];
    __shared__ float tb[9];
    __shared__ float red[256];

    const int c = blockIdx.x;
    const int b = blockIdx.y;
    const int tid = threadIdx.x;

    const bf16* y1p = Y1 + ((size_t)b * CH + c) * HWP;
    const bf16* xp  = Xf + ((size_t)b * CH + c) * HWP;

    for (int idx = tid; idx < 66 * 66; idx += 256) {
        int hh = idx / 66 - 1;
        int ww = idx % 66 - 1;
        bool ok = (hh >= 0 && hh < 64 && ww >= 0 && ww < 64);
        sy[idx] = ok ? __bfloat162float(y1p[hh * 64 + ww]) : 0.f;
        sx[idx] = ok ? __bfloat162float(xp[hh * 64 + ww]) : 0.f;
    }
    if (tid < 81) taps[tid] = ws2[c * 81 + tid];
    if (tid < 9)  tb[tid]   = bs2[c * 9 + tid];
    __syncthreads();

    float sum = 0.f;
    for (int pp = tid; pp < HWP; pp += 256) {
        int hq = pp >> 6;
        int wq = pp & 63;
        float ywin[9], xwin[9];
#pragma unroll
        for (int di = 0; di < 3; di++)
#pragma unroll
            for (int dj = 0; dj < 3; dj++) {
                ywin[di * 3 + dj] = sy[(hq + di) * 66 + (wq + dj)];
                xwin[di * 3 + dj] = sx[(hq + di) * 66 + (wq + dj)];
            }
        float o = 0.f;
#pragma unroll
        for (int kk = 0; kk < 9; kk++) {
            float ks = tb[kk];
#pragma unroll
            for (int r = 0; r < 9; r++)
                ks = fmaf(ywin[r], taps[kk * 9 + r], ks);
            o = fmaf(xwin[kk], ks, o);
        }
        Out[((size_t)b * CH + c) * HWP + pp] = __float2bfloat16(o);
        sum += o;
    }
    red[tid] = sum;
    __syncthreads();
    for (int s = 128; s > 0; s >>= 1) {
        if (tid < s) red[tid] += red[tid + s];
        __syncthreads();
    }
    if (tid == 0) Mean[b * CH + c] = red[0] * (1.f / HWP);
}

// ============================================================
// SE gate (one block per batch element)
// ============================================================
__global__ __launch_bounds__(192) void se_kernel(
    const float* __restrict__ Mean,
    const float* __restrict__ wc0, const float* __restrict__ bc0,
    const float* __restrict__ wc1, const float* __restrict__ bc1,
    float* __restrict__ Gate)
{
    __shared__ float m[CH];
    __shared__ float hbuf[CH];
    const int b = blockIdx.x;
    const int i = threadIdx.x;
    m[i] = Mean[b * CH + i];
    __syncthreads();
    float s = bc0[i];
    const float* w = wc0 + (size_t)i * CH;
#pragma unroll 8
    for (int j = 0; j < CH; j++) s = fmaf(w[j], m[j], s);
    hbuf[i] = s > 0.f ? s : 0.1f * s;
    __syncthreads();
    float s2 = bc1[i];
    const float* w2 = wc1 + (size_t)i * CH;
#pragma unroll 8
    for (int j = 0; j < CH; j++) s2 = fmaf(w2[j], hbuf[j], s2);
    Gate[b * CH + i] = 1.f / (1.f + expf(-s2));
}

extern "C" void kernel_launch(void* const* d_in, const int* in_sizes, int n_in,
                              void* d_out, int out_size)
{
    const float* input = (const float*)d_in[0];
    const float* lc    = (const float*)d_in[1];
    const int*   mask  = (const int*)d_in[2];
    const float* w0  = (const float*)d_in[3];
    const float* b0  = (const float*)d_in[4];
    const float* w1  = (const float*)d_in[5];
    const float* b1  = (const float*)d_in[6];
    const float* ws0 = (const float*)d_in[7];
    const float* bs0 = (const float*)d_in[8];
    const float* ws1 = (const float*)d_in[9];
    const float* bs1 = (const float*)d_in[10];
    const float* ws2 = (const float*)d_in[11];
    const float* bs2 = (const float*)d_in[12];
    const float* wc0 = (const float*)d_in[13];
    const float* bc0 = (const float*)d_in[14];
    const float* wc1 = (const float*)d_in[15];
    const float* bc1 = (const float*)d_in[16];
    const float* wo  = (const float*)d_in[17];
    const float* bo  = (const float*)d_in[18];
    float* out = (float*)d_out;

    bf16 *pb0, *pb1, *pb2, *pb3, *pw0b, *pw1b, *pwsxb, *pwob, *pwrb;
    float *pT, *pMean, *pGate;
    cudaGetSymbolAddress((void**)&pb0, g_b0);
    cudaGetSymbolAddress((void**)&pb1, g_b1);
    cudaGetSymbolAddress((void**)&pb2, g_b2);
    cudaGetSymbolAddress((void**)&pb3, g_b3);
    cudaGetSymbolAddress((void**)&pw0b, g_w0b);
    cudaGetSymbolAddress((void**)&pw1b, g_w1b);
    cudaGetSymbolAddress((void**)&pwsxb, g_wsxb);
    cudaGetSymbolAddress((void**)&pwob, g_wob);
    cudaGetSymbolAddress((void**)&pwrb, g_wrb);
    cudaGetSymbolAddress((void**)&pT, g_T);
    cudaGetSymbolAddress((void**)&pMean, g_mean);
    cudaGetSymbolAddress((void**)&pGate, g_gate);

    const int conv_smem  = 2 * 13824 * 2 + 2 * PSTAGEW * 4;        // 83,456 B
    const int chain_smem = (2 * BBUF + 2 * APAN) * 2;              // 155,648 B
    cudaFuncSetAttribute(conv3x3_tc,
                         cudaFuncAttributeMaxDynamicSharedMemorySize, conv_smem);
    cudaFuncSetAttribute(chain3_tc,
                         cudaFuncAttributeMaxDynamicSharedMemorySize, chain_smem);

    // 0) prep weights (bf16 + reorder)
    prep_weights<<<(13 * CH * CH + 255) / 256, 256>>>(
        w0, w1, ws0, ws1, wo, pw0b, pw1b, pwsxb, pwob, pwrb);
    // 1) T table
    tgen_kernel<<<dim3(BSZ * MASKN, 6), 256>>>(lc, ws0, pT);
    // 2) fused chain: v -> x -> y0  (x to g_b1, y0 interleaved to g_b2)
    chain3_tc<<<dim3(32, 1, 8), 256, chain_smem>>>(
        input, pw0b, pw1b, pwsxb, b0, b1, bs0, mask, pT, pb1, pb2);
    // 3) y1 = lrelu(conv3x3(y0, ws1, bs1))
    conv3x3_tc<<<dim3(16, 3, 8), 128, conv_smem>>>(pb2, pwrb, bs1, pb3);
    // 4) out_feat = dynamic_conv(x, depthwise(y1)) ; per-(b,c) mean
    dyn_kernel<<<dim3(CH, BSZ), 256>>>(pb3, pb1, ws2, bs2, pb0, pMean);
    // 5) gate
    se_kernel<<<BSZ, 192>>>(pMean, wc0, bc0, wc1, bc1, pGate);
    // 6) out = conv1x1(gate*out_feat, wo, bo) + input
    gemm_final_tc<<<dim3(16, 3, 8), 256>>>(
        pb0, pwob, bo, out, pGate, input);
}

// round 11
// speedup vs baseline: 1.0927x; 1.0927x over previous
#include <cuda_runtime.h>
#include <cuda_bf16.h>
#include <math.h>
#include <stdint.h>

#define BSZ 8
#define CH 192
#define HWP 4096
#define MASKN 16

typedef __nv_bfloat16 bf16;

// ---- scratch (static device globals) ----
__device__ bf16 g_b0[BSZ * CH * HWP];    // dyn-conv output
__device__ bf16 g_b1[BSZ * CH * HWP];    // x
__device__ bf16 g_b2[BSZ * CH * HWP];    // y0 (channel-pair interleaved!)
__device__ bf16 g_b3[BSZ * CH * HWP];    // y1
__device__ bf16 g_w0b[CH * CH];
__device__ bf16 g_w1b[CH * CH];
__device__ bf16 g_wsxb[CH * CH];         // x-half of ws0
__device__ bf16 g_wob[CH * CH];
__device__ bf16 g_wrb[9 * CH * CH];      // reordered ws1: [r][co][ci]
__device__ float g_T[BSZ * MASKN * CH];
__device__ float g_mean[BSZ * CH];
__device__ float g_gate[BSZ * CH];

// ---- bf16 mma m16n8k16 (row.col), fp32 accumulate ----
__device__ __forceinline__ void mma_bf16(float* c, const uint32_t* a, uint32_t b0, uint32_t b1)
{
    asm("mma.sync.aligned.m16n8k16.row.col.f32.bf16.bf16.f32 "
        "{%0,%1,%2,%3}, {%4,%5,%6,%7}, {%8,%9}, {%0,%1,%2,%3};\n"
        : "+f"(c[0]), "+f"(c[1]), "+f"(c[2]), "+f"(c[3])
        : "r"(a[0]), "r"(a[1]), "r"(a[2]), "r"(a[3]), "r"(b0), "r"(b1));
}

#define LDMX2T(b0, b1, addr) \
    asm volatile("ldmatrix.sync.aligned.m8n8.x2.trans.shared.b16 {%0,%1}, [%2];\n" \
                 : "=r"(b0), "=r"(b1) : "r"(addr))

#define LDMX4(r0, r1, r2, r3, addr) \
    asm volatile("ldmatrix.sync.aligned.m8n8.x4.shared.b16 {%0,%1,%2,%3}, [%4];\n" \
                 : "=r"(r0), "=r"(r1), "=r"(r2), "=r"(r3) : "r"(addr))

#define CP16(dst, src) \
    asm volatile("cp.async.cg.shared.global [%0], [%1], 16;\n" :: "r"(dst), "l"(src))
#define CP_COMMIT() asm volatile("cp.async.commit_group;\n")
#define CP_WAIT0()  asm volatile("cp.async.wait_group 0;\n")

__device__ __forceinline__ __nv_bfloat162 u2bf2(uint32_t u)
{
    return *reinterpret_cast<__nv_bfloat162*>(&u);
}

// ============================================================
// Fused chain: v = lrelu(W0@in), x = W1@v, y0 = lrelu(Wsx@x + T + bs0)
// (R9 config: 512 threads = 16 warps, warp tile 32x32, grid (16,1,8))
// ============================================================
#define BST 264
#define BBUF (CH * BST)
#define AST 200

__global__ __launch_bounds__(512) void chain3_tc(
    const float* __restrict__ input,
    const bf16* __restrict__ W0, const bf16* __restrict__ W1,
    const bf16* __restrict__ Wsx,
    const float* __restrict__ bias0, const float* __restrict__ bias1,
    const float* __restrict__ bias2,
    const int* __restrict__ mask, const float* __restrict__ Tt,
    bf16* __restrict__ Xout, bf16* __restrict__ Y0i)
{
    extern __shared__ __align__(16) bf16 sm[];
    bf16* Bbuf0 = sm;
    bf16* Bbuf1 = sm + BBUF;
    bf16* As    = sm + 2 * BBUF;

    const int b   = blockIdx.z;
    const int n0  = blockIdx.x * 256;
    const int tid = threadIdx.x;
    const int lane = tid & 31;
    const int warp = tid >> 5;     // 0..15
    const int wm = warp >> 3;      // 0..1
    const int wn = warp & 7;       // 0..7
    const int tq = lane & 3;
    const int gq = lane >> 2;
    const int lg = lane >> 3;
    const int arow = (lg & 1) * 8 + (lane & 7);
    const int akoff = (lg >> 1) * 8;

    const float* inb = input + (size_t)b * CH * HWP;
    for (int idx = tid; idx < CH * 128; idx += 512) {
        int ch = idx >> 7, pu = idx & 127;
        float2 v = *(const float2*)(inb + (size_t)ch * HWP + n0 + 2 * pu);
        __nv_bfloat162 o;
        o.x = __float2bfloat16(v.x);
        o.y = __float2bfloat16(v.y);
        *(__nv_bfloat162*)(Bbuf0 + ch * BST + 2 * pu) = o;
    }
    __syncthreads();

    uint32_t s_as = (uint32_t)__cvta_generic_to_shared(As);

#pragma unroll 1
    for (int ph = 0; ph < 3; ph++) {
        const bf16* W = (ph == 0) ? W0 : (ph == 1 ? W1 : Wsx);
        const float* bias = (ph == 0) ? bias0 : (ph == 1 ? bias1 : bias2);
        bf16* Bsrc = (ph == 1) ? Bbuf1 : Bbuf0;
        bf16* Bdst = (ph == 0) ? Bbuf1 : Bbuf0;
        uint32_t s_bsrc = (uint32_t)__cvta_generic_to_shared(Bsrc);

#pragma unroll 1
        for (int mc = 0; mc < 3; mc++) {
            const int m0 = mc * 64;

#pragma unroll
            for (int t = 0; t < 3; t++) {
                int idx = tid + t * 512;   // 1536 chunks exactly
                int i = idx / 24, c8 = (idx % 24) * 8;
                CP16(s_as + (uint32_t)(i * AST + c8) * 2,
                     W + (size_t)(m0 + i) * CH + c8);
            }
            CP_COMMIT();
            CP_WAIT0();
            __syncthreads();

            float c[2][4][4];
#pragma unroll
            for (int i = 0; i < 2; i++)
#pragma unroll
                for (int j = 0; j < 4; j++)
#pragma unroll
                    for (int q = 0; q < 4; q++) c[i][j][q] = 0.f;

#pragma unroll
            for (int kt = 0; kt < CH; kt += 16) {
                uint32_t a[2][4];
#pragma unroll
                for (int mt = 0; mt < 2; mt++) {
                    uint32_t aadr = s_as
                        + (uint32_t)((wm * 32 + mt * 16 + arow) * AST + kt + akoff) * 2;
                    LDMX4(a[mt][0], a[mt][1], a[mt][2], a[mt][3], aadr);
                }
                uint32_t badr = s_bsrc
                    + (uint32_t)((kt + (lane & 15)) * BST + wn * 32) * 2;
#pragma unroll
                for (int nt = 0; nt < 4; nt++) {
                    uint32_t bf0, bf1;
                    LDMX2T(bf0, bf1, badr + nt * 16);
                    mma_bf16(c[0][nt], a[0], bf0, bf1);
                    mma_bf16(c[1][nt], a[1], bf0, bf1);
                }
            }

#pragma unroll
            for (int mt = 0; mt < 2; mt++) {
#pragma unroll
                for (int half = 0; half < 2; half++) {
                    int co = m0 + wm * 32 + mt * 16 + gq + half * 8;
                    float bi = bias[co];
#pragma unroll
                    for (int nt = 0; nt < 4; nt++) {
                        int ploc = wn * 32 + nt * 8 + tq * 2;
                        float v0 = c[mt][nt][half * 2 + 0] + bi;
                        float v1 = c[mt][nt][half * 2 + 1] + bi;
                        if (ph == 2) {
                            int p = n0 + ploc;
                            int mk0 = mask[b * HWP + p];
                            int mk1 = mask[b * HWP + p + 1];
                            v0 += Tt[(b * MASKN + mk0) * CH + co];
                            v1 += Tt[(b * MASKN + mk1) * CH + co];
                        }
                        if (ph != 1) {
                            v0 = v0 > 0.f ? v0 : 0.1f * v0;
                            v1 = v1 > 0.f ? v1 : 0.1f * v1;
                        }
                        if (ph < 2) {
                            __nv_bfloat162 o;
                            o.x = __float2bfloat16(v0);
                            o.y = __float2bfloat16(v1);
                            *(__nv_bfloat162*)(Bdst + co * BST + ploc) = o;
                        }
                        if (ph == 1) {
                            __nv_bfloat162 o;
                            o.x = __float2bfloat16(v0);
                            o.y = __float2bfloat16(v1);
                            *(__nv_bfloat162*)(Xout + ((size_t)b * CH + co) * HWP + n0 + ploc) = o;
                        }
                        if (ph == 2) {
                            size_t w = ((size_t)b * (CH / 2) + (co >> 1)) * HWP + n0 + ploc;
                            bf16* dst = Y0i + w * 2 + (co & 1);
                            dst[0] = __float2bfloat16(v0);
                            dst[2] = __float2bfloat16(v1);
                        }
                    }
                }
            }
            __syncthreads();
        }
    }
}

// ============================================================
// FINAL 1x1 conv GEMM (gate folded into A; fp32 out + residual).
// ============================================================
__global__ __launch_bounds__(256) void gemm_final_tc(
    const bf16* __restrict__ X, const bf16* __restrict__ Wb,
    const float* __restrict__ bias, float* __restrict__ Y,
    const float* __restrict__ gate, const float* __restrict__ resid)
{
    __shared__ __align__(16) bf16 As[2][64][24];
    __shared__ __align__(16) bf16 Bs[2][16][264];
    __shared__ float sgate[CH];

    const int b   = blockIdx.z;
    const int m0  = blockIdx.y * 64;
    const int n0  = blockIdx.x * 256;
    const int tid = threadIdx.x;
    const int lane = tid & 31;
    const int warp = tid >> 5;
    const int wm = warp >> 2;
    const int wn = warp & 3;
    const int tq = lane & 3;
    const int gq = lane >> 2;
    const int lg = lane >> 3;
    const int arow = (lg & 1) * 8 + (lane & 7);
    const int akoff = (lg >> 1) * 8;

    const bf16* Xb = X + (size_t)b * CH * HWP;

    if (tid < CH) sgate[tid] = gate[b * CH + tid];
    __syncthreads();

    uint32_t s_as = (uint32_t)__cvta_generic_to_shared(&As[0][0][0]);
    uint32_t s_bs = (uint32_t)__cvta_generic_to_shared(&Bs[0][0][0]);

    float c[2][8][4];
#pragma unroll
    for (int i = 0; i < 2; i++)
#pragma unroll
        for (int j = 0; j < 8; j++)
#pragma unroll
            for (int q = 0; q < 4; q++) c[i][j][q] = 0.f;

    auto issue = [&](int kt, int st) {
        if (tid < 128) {
            int co = tid >> 1, h8 = (tid & 1) * 8;
            const bf16* src = Wb + (size_t)(m0 + co) * CH + kt + h8;
            bf16 tmp[8];
            *(uint4*)tmp = *(const uint4*)src;
            bf16 dst8[8];
#pragma unroll
            for (int i = 0; i < 8; i++)
                dst8[i] = __float2bfloat16(__bfloat162float(tmp[i]) * sgate[kt + h8 + i]);
            *(uint4*)&As[st][co][h8] = *(uint4*)dst8;
        }
#pragma unroll
        for (int t = 0; t < 2; t++) {
            int idx = tid + t * 256;
            int k = idx >> 5, q = idx & 31;
            CP16(s_bs + (uint32_t)(st * 4224 + k * 264 + q * 8) * 2,
                 Xb + (size_t)(kt + k) * HWP + n0 + q * 8);
        }
    };

    issue(0, 0);
    CP_COMMIT();

    for (int step = 0; step < 12; step++) {
        CP_WAIT0();
        __syncthreads();
        if (step < 11) { issue((step + 1) * 16, (step + 1) & 1); CP_COMMIT(); }

        uint32_t sAc = s_as + (step & 1) * 1536 * 2;
        uint32_t sBc = s_bs + (step & 1) * 4224 * 2;

        uint32_t a[2][4];
#pragma unroll
        for (int mt = 0; mt < 2; mt++) {
            uint32_t aadr = sAc + (uint32_t)((wm * 32 + mt * 16 + arow) * 24 + akoff) * 2;
            LDMX4(a[mt][0], a[mt][1], a[mt][2], a[mt][3], aadr);
        }
        uint32_t badr = sBc + (uint32_t)((lane & 15) * 264 + wn * 64) * 2;
#pragma unroll
        for (int nt = 0; nt < 8; nt++) {
            uint32_t b0, b1;
            LDMX2T(b0, b1, badr + nt * 16);
            mma_bf16(c[0][nt], a[0], b0, b1);
            mma_bf16(c[1][nt], a[1], b0, b1);
        }
    }

#pragma unroll
    for (int mt = 0; mt < 2; mt++) {
#pragma unroll
        for (int half = 0; half < 2; half++) {
            int co = m0 + wm * 32 + mt * 16 + gq + half * 8;
            float bi = bias[co];
#pragma unroll
            for (int nt = 0; nt < 8; nt++) {
                int p = n0 + wn * 64 + nt * 8 + tq * 2;
                size_t off = ((size_t)b * CH + co) * HWP + p;
                float v0 = c[mt][nt][half * 2 + 0] + bi + resid[off];
                float v1 = c[mt][nt][half * 2 + 1] + bi + resid[off + 1];
                *(float2*)(Y + off) = make_float2(v0, v1);
            }
        }
    }
}

// ============================================================
// 3x3 conv, bf16 TC, channel-pair interleaved B, ldmatrix A.
// 128 threads = 4 warps, warp tile 64x64, 2 CTAs/SM. (unchanged R9)
// ============================================================
#define PSTW 440
#define PSTAGEW (8 * PSTW)
__global__ __launch_bounds__(128, 2) void conv3x3_tc(
    const bf16* __restrict__ Y0i, const bf16* __restrict__ Wr,
    const float* __restrict__ bias, bf16* __restrict__ Y)
{
    extern __shared__ __align__(16) bf16 smem[];
    bf16* Asb = smem;
    uint32_t* Psb = (uint32_t*)(smem + 2 * 13824);

    const int b    = blockIdx.z;
    const int m0   = blockIdx.y * 64;
    const int tile = blockIdx.x;
    const int row0 = tile * 4;
    const int n0   = tile * 256;
    const int tid  = threadIdx.x;
    const int lane = tid & 31;
    const int wn   = tid >> 5;
    const int tq = lane & 3;
    const int gq = lane >> 2;
    const int lg = lane >> 3;
    const int arow = (lg & 1) * 8 + (lane & 7);
    const int akoff = (lg >> 1) * 8;

    const uint32_t* Xw = (const uint32_t*)Y0i + (size_t)b * (CH / 2) * HWP;

    for (int i = tid; i < 2 * PSTAGEW; i += 128) Psb[i] = 0u;
    __syncthreads();

    uint32_t s_as = (uint32_t)__cvta_generic_to_shared(Asb);
    uint32_t s_ps = (uint32_t)__cvta_generic_to_shared(Psb);

    float c[4][8][4];
#pragma unroll
    for (int i = 0; i < 4; i++)
#pragma unroll
        for (int j = 0; j < 8; j++)
#pragma unroll
            for (int q = 0; q < 4; q++) c[i][j][q] = 0.f;

    auto issue = [&](int kt, int st) {
        uint32_t ab = s_as + st * (13824 * 2);
#pragma unroll
        for (int t = 0; t < 9; t++) {
            int idx = tid + t * 128;
            int r = idx >> 7;
            int rem = idx & 127;
            int co = rem >> 1, h8 = (rem & 1) * 8;
            CP16(ab + (uint32_t)((r * 64 + co) * 24 + h8) * 2,
                 Wr + ((size_t)r * CH + m0 + co) * CH + kt + h8);
        }
        uint32_t pb = s_ps + st * (PSTAGEW * 4);
        const int cp0 = kt >> 1;
#pragma unroll
        for (int t = 0; t < 6; t++) {
            int idx = tid + t * 128;
            int m = idx / 96;
            int rem = idx - m * 96;
            int rr = rem >> 4;
            int q  = rem & 15;
            int hh = row0 + rr - 1;
            if (hh >= 0 && hh < 64) {
                CP16(pb + (uint32_t)(m * PSTW + rr * 72 + 8 + q * 4) * 4,
                     Xw + (size_t)(cp0 + m) * HWP + hh * 64 + q * 4);
            }
        }
    };

    issue(0, 0);
    CP_COMMIT();

    for (int step = 0; step < 12; step++) {
        CP_WAIT0();
        __syncthreads();
        if (step < 11) { issue((step + 1) * 16, (step + 1) & 1); CP_COMMIT(); }

        uint32_t sAc = s_as + (step & 1) * (13824 * 2);
        const uint32_t* Pw = Psb + (step & 1) * PSTAGEW;

#pragma unroll 1
        for (int r = 0; r < 9; r++) {
            const int di = r / 3, dj = r - (r / 3) * 3;

            uint32_t a[4][4];
#pragma unroll
            for (int mt = 0; mt < 4; mt++) {
                uint32_t aadr = sAc
                    + (uint32_t)((r * 64 + mt * 16 + arow) * 24 + akoff) * 2;
                LDMX4(a[mt][0], a[mt][1], a[mt][2], a[mt][3], aadr);
            }
            const uint32_t* pr0 = Pw + tq * PSTW + (wn + di) * 72 + gq + dj + 7;
            const uint32_t* pr1 = pr0 + 4 * PSTW;
#pragma unroll
            for (int nt = 0; nt < 8; nt++) {
                uint32_t b0 = pr0[nt * 8];
                uint32_t b1 = pr1[nt * 8];
#pragma unroll
                for (int mt = 0; mt < 4; mt++)
                    mma_bf16(c[mt][nt], a[mt], b0, b1);
            }
        }
    }

#pragma unroll
    for (int mt = 0; mt < 4; mt++) {
#pragma unroll
        for (int half = 0; half < 2; half++) {
            int co = m0 + mt * 16 + gq + half * 8;
            float bi = bias[co];
#pragma unroll
            for (int nt = 0; nt < 8; nt++) {
                int p = n0 + wn * 64 + nt * 8 + tq * 2;
                float v0 = c[mt][nt][half * 2 + 0] + bi;
                float v1 = c[mt][nt][half * 2 + 1] + bi;
                v0 = v0 > 0.f ? v0 : 0.1f * v0;
                v1 = v1 > 0.f ? v1 : 0.1f * v1;
                __nv_bfloat162 o;
                o.x = __float2bfloat16(v0);
                o.y = __float2bfloat16(v1);
                *(__nv_bfloat162*)&Y[((size_t)b * CH + co) * HWP + p] = o;
            }
        }
    }
}

// ============================================================
// prep: convert weights to bf16 (+ reorder ws1 -> [r][co][ci])
// ============================================================
__global__ void prep_weights(
    const float* __restrict__ w0, const float* __restrict__ w1,
    const float* __restrict__ ws0, const float* __restrict__ ws1,
    const float* __restrict__ wo,
    bf16* __restrict__ w0b, bf16* __restrict__ w1b,
    bf16* __restrict__ wsxb, bf16* __restrict__ wob,
    bf16* __restrict__ wrb)
{
    const int S = CH * CH;
    int idx = blockIdx.x * 256 + threadIdx.x;
    if (idx < S) {
        w0b[idx] = __float2bfloat16(w0[idx]);
    } else if (idx < 2 * S) {
        int i = idx - S;
        w1b[i] = __float2bfloat16(w1[i]);
    } else if (idx < 3 * S) {
        int i = idx - 2 * S;
        int co = i / CH, ci = i % CH;
        wsxb[i] = __float2bfloat16(ws0[(size_t)co * (2 * CH) + ci]);
    } else if (idx < 4 * S) {
        int i = idx - 3 * S;
        wob[i] = __float2bfloat16(wo[i]);
    } else if (idx < 4 * S + 9 * S) {
        int i = idx - 4 * S;
        int ci = i % CH;
        int co = (i / CH) % CH;
        int r  = i / S;
        wrb[i] = __float2bfloat16(ws1[((size_t)co * CH + ci) * 9 + r]);
    }
}

// ============================================================
// T[b,m,co] = sum_ci ws0[co, 192+ci] * list_center[b,m,ci]
// ============================================================
__global__ __launch_bounds__(256) void tgen_kernel(
    const float* __restrict__ lc, const float* __restrict__ ws0,
    float* __restrict__ T)
{
    __shared__ float cvec[CH];
    const int bm = blockIdx.x;
    const int cg = blockIdx.y;
    const int tid = threadIdx.x;
    if (tid < CH) cvec[tid] = lc[(size_t)bm * CH + tid];
    __syncthreads();
    const int warp = tid >> 5, lane = tid & 31;
    const int co0 = cg * 32 + warp * 4;
#pragma unroll
    for (int q = 0; q < 4; q++) {
        const float* w = ws0 + (size_t)(co0 + q) * (2 * CH) + CH;
        float s = 0.f;
#pragma unroll
        for (int j = lane; j < CH; j += 32) s = fmaf(w[j], cvec[j], s);
#pragma unroll
        for (int o = 16; o; o >>= 1) s += __shfl_xor_sync(0xffffffffu, s, o);
        if (lane == 0) T[bm * CH + co0 + q] = s;
    }
}

// ============================================================
// Fused depthwise-3x3 (k_sp) + dynamic conv + mean reduce.
// bf16x2 HFMA2 arithmetic: 2 pixels per step, 90 HFMA2 per pair
// (vs 198 FFMA). Neighbor pairs built from 2 aligned LDS.32 + shift.
// ============================================================
#define DROW 68   // halo row stride in halves (34 words)
__global__ __launch_bounds__(256) void dyn_kernel(
    const bf16* __restrict__ Y1, const bf16* __restrict__ Xf,
    const float* __restrict__ ws2, const float* __restrict__ bs2,
    bf16* __restrict__ Out, float* __restrict__ Mean)
{
    __shared__ __align__(4) bf16 sy[66 * DROW];
    __shared__ __align__(4) bf16 sx[66 * DROW];
    __shared__ __nv_bfloat162 taps2[81];
    __shared__ __nv_bfloat162 tb2[9];
    __shared__ float red[256];

    const int c = blockIdx.x;
    const int b = blockIdx.y;
    const int tid = threadIdx.x;

    const bf16* y1p = Y1 + ((size_t)b * CH + c) * HWP;
    const bf16* xp  = Xf + ((size_t)b * CH + c) * HWP;

    for (int idx = tid; idx < 66 * DROW; idx += 256) {
        int row = idx / DROW;
        int col = idx - row * DROW;
        int hh = row - 1, ww = col - 1;
        bool ok = (hh >= 0 && hh < 64 && ww >= 0 && ww < 64);
        sy[idx] = ok ? y1p[hh * 64 + ww] : __float2bfloat16(0.f);
        sx[idx] = ok ? xp[hh * 64 + ww] : __float2bfloat16(0.f);
    }
    if (tid < 81) {
        bf16 h = __float2bfloat16(ws2[c * 81 + tid]);
        taps2[tid] = __nv_bfloat162(h, h);
    }
    if (tid < 9) {
        bf16 h = __float2bfloat16(bs2[c * 9 + tid]);
        tb2[tid] = __nv_bfloat162(h, h);
    }
    __syncthreads();

    float sum = 0.f;
    for (int pp2 = tid; pp2 < 2048; pp2 += 256) {
        const int hq = pp2 >> 5;            // image row
        const int c0 = (pp2 & 31) * 2;      // even image/halo col base
        const int w0i = c0 >> 1;            // word index

        __nv_bfloat162 yp[9], xpr[9];
#pragma unroll
        for (int di = 0; di < 3; di++) {
            const uint32_t* ry = (const uint32_t*)(sy + (hq + di) * DROW);
            const uint32_t* rx = (const uint32_t*)(sx + (hq + di) * DROW);
            uint32_t ya = ry[w0i], yb = ry[w0i + 1];
            uint32_t xa = rx[w0i], xb = rx[w0i + 1];
            yp[di * 3 + 0] = u2bf2(ya);
            yp[di * 3 + 1] = u2bf2((ya >> 16) | (yb << 16));
            yp[di * 3 + 2] = u2bf2(yb);
            xpr[di * 3 + 0] = u2bf2(xa);
            xpr[di * 3 + 1] = u2bf2((xa >> 16) | (xb << 16));
            xpr[di * 3 + 2] = u2bf2(xb);
        }

        __nv_bfloat162 o = __nv_bfloat162(__float2bfloat16(0.f), __float2bfloat16(0.f));
#pragma unroll
        for (int kk = 0; kk < 9; kk++) {
            __nv_bfloat162 ks = tb2[kk];
#pragma unroll
            for (int r = 0; r < 9; r++)
                ks = __hfma2(yp[r], taps2[kk * 9 + r], ks);
            o = __hfma2(xpr[kk], ks, o);
        }

        int p0 = hq * 64 + c0;
        *(__nv_bfloat162*)(&Out[((size_t)b * CH + c) * HWP + p0]) = o;
        sum += __bfloat162float(o.x) + __bfloat162float(o.y);
    }
    red[tid] = sum;
    __syncthreads();
    for (int s = 128; s > 0; s >>= 1) {
        if (tid < s) red[tid] += red[tid + s];
        __syncthreads();
    }
    if (tid == 0) Mean[b * CH + c] = red[0] * (1.f / HWP);
}

// ============================================================
// SE gate (one block per batch element)
// ============================================================
__global__ __launch_bounds__(192) void se_kernel(
    const float* __restrict__ Mean,
    const float* __restrict__ wc0, const float* __restrict__ bc0,
    const float* __restrict__ wc1, const float* __restrict__ bc1,
    float* __restrict__ Gate)
{
    __shared__ float m[CH];
    __shared__ float hbuf[CH];
    const int b = blockIdx.x;
    const int i = threadIdx.x;
    m[i] = Mean[b * CH + i];
    __syncthreads();
    float s = bc0[i];
    const float* w = wc0 + (size_t)i * CH;
#pragma unroll 8
    for (int j = 0; j < CH; j++) s = fmaf(w[j], m[j], s);
    hbuf[i] = s > 0.f ? s : 0.1f * s;
    __syncthreads();
    float s2 = bc1[i];
    const float* w2 = wc1 + (size_t)i * CH;
#pragma unroll 8
    for (int j = 0; j < CH; j++) s2 = fmaf(w2[j], hbuf[j], s2);
    Gate[b * CH + i] = 1.f / (1.f + expf(-s2));
}

extern "C" void kernel_launch(void* const* d_in, const int* in_sizes, int n_in,
                              void* d_out, int out_size)
{
    const float* input = (const float*)d_in[0];
    const float* lc    = (const float*)d_in[1];
    const int*   mask  = (const int*)d_in[2];
    const float* w0  = (const float*)d_in[3];
    const float* b0  = (const float*)d_in[4];
    const float* w1  = (const float*)d_in[5];
    const float* b1  = (const float*)d_in[6];
    const float* ws0 = (const float*)d_in[7];
    const float* bs0 = (const float*)d_in[8];
    const float* ws1 = (const float*)d_in[9];
    const float* bs1 = (const float*)d_in[10];
    const float* ws2 = (const float*)d_in[11];
    const float* bs2 = (const float*)d_in[12];
    const float* wc0 = (const float*)d_in[13];
    const float* bc0 = (const float*)d_in[14];
    const float* wc1 = (const float*)d_in[15];
    const float* bc1 = (const float*)d_in[16];
    const float* wo  = (const float*)d_in[17];
    const float* bo  = (const float*)d_in[18];
    float* out = (float*)d_out;

    bf16 *pb0, *pb1, *pb2, *pb3, *pw0b, *pw1b, *pwsxb, *pwob, *pwrb;
    float *pT, *pMean, *pGate;
    cudaGetSymbolAddress((void**)&pb0, g_b0);
    cudaGetSymbolAddress((void**)&pb1, g_b1);
    cudaGetSymbolAddress((void**)&pb2, g_b2);
    cudaGetSymbolAddress((void**)&pb3, g_b3);
    cudaGetSymbolAddress((void**)&pw0b, g_w0b);
    cudaGetSymbolAddress((void**)&pw1b, g_w1b);
    cudaGetSymbolAddress((void**)&pwsxb, g_wsxb);
    cudaGetSymbolAddress((void**)&pwob, g_wob);
    cudaGetSymbolAddress((void**)&pwrb, g_wrb);
    cudaGetSymbolAddress((void**)&pT, g_T);
    cudaGetSymbolAddress((void**)&pMean, g_mean);
    cudaGetSymbolAddress((void**)&pGate, g_gate);

    const int conv_smem  = 2 * 13824 * 2 + 2 * PSTAGEW * 4;        // 83,456 B
    const int chain_smem = (2 * BBUF + 64 * AST) * 2;              // 228,352 B
    cudaFuncSetAttribute(conv3x3_tc,
                         cudaFuncAttributeMaxDynamicSharedMemorySize, conv_smem);
    cudaFuncSetAttribute(chain3_tc,
                         cudaFuncAttributeMaxDynamicSharedMemorySize, chain_smem);

    // 0) prep weights (bf16 + reorder)
    prep_weights<<<(13 * CH * CH + 255) / 256, 256>>>(
        w0, w1, ws0, ws1, wo, pw0b, pw1b, pwsxb, pwob, pwrb);
    // 1) T table
    tgen_kernel<<<dim3(BSZ * MASKN, 6), 256>>>(lc, ws0, pT);
    // 2) fused chain: v -> x -> y0  (x to g_b1, y0 interleaved to g_b2)
    chain3_tc<<<dim3(16, 1, 8), 512, chain_smem>>>(
        input, pw0b, pw1b, pwsxb, b0, b1, bs0, mask, pT, pb1, pb2);
    // 3) y1 = lrelu(conv3x3(y0, ws1, bs1))
    conv3x3_tc<<<dim3(16, 3, 8), 128, conv_smem>>>(pb2, pwrb, bs1, pb3);
    // 4) out_feat = dynamic_conv(x, depthwise(y1)) ; per-(b,c) mean
    dyn_kernel<<<dim3(CH, BSZ), 256>>>(pb3, pb1, ws2, bs2, pb0, pMean);
    // 5) gate
    se_kernel<<<BSZ, 192>>>(pMean, wc0, bc0, wc1, bc1, pGate);
    // 6) out = conv1x1(gate*out_feat, wo, bo) + input
    gemm_final_tc<<<dim3(16, 3, 8), 256>>>(
        pb0, pwob, bo, out, pGate, input);
}

// round 12
// speedup vs baseline: 1.1267x; 1.0312x over previous
#include <cuda_runtime.h>
#include <cuda_bf16.h>
#include <math.h>
#include <stdint.h>

#define BSZ 8
#define CH 192
#define HWP 4096
#define MASKN 16

typedef __nv_bfloat16 bf16;

// ---- scratch (static device globals) ----
__device__ bf16 g_b0[BSZ * CH * HWP];    // dyn-conv output
__device__ bf16 g_b1[BSZ * CH * HWP];    // x
__device__ bf16 g_b2[BSZ * CH * HWP];    // y0 (channel-pair interleaved!)
__device__ bf16 g_b3[BSZ * CH * HWP];    // y1
__device__ bf16 g_w0b[CH * CH];
__device__ bf16 g_w1b[CH * CH];
__device__ bf16 g_wsxb[CH * CH];         // x-half of ws0
__device__ bf16 g_wob[CH * CH];
__device__ bf16 g_wrb[9 * CH * CH];      // reordered ws1: [r][co][ci]
__device__ float g_T[BSZ * MASKN * CH];
__device__ float g_mean[BSZ * CH];
__device__ float g_gate[BSZ * CH];

// ---- bf16 mma m16n8k16 (row.col), fp32 accumulate ----
__device__ __forceinline__ void mma_bf16(float* c, const uint32_t* a, uint32_t b0, uint32_t b1)
{
    asm("mma.sync.aligned.m16n8k16.row.col.f32.bf16.bf16.f32 "
        "{%0,%1,%2,%3}, {%4,%5,%6,%7}, {%8,%9}, {%0,%1,%2,%3};\n"
        : "+f"(c[0]), "+f"(c[1]), "+f"(c[2]), "+f"(c[3])
        : "r"(a[0]), "r"(a[1]), "r"(a[2]), "r"(a[3]), "r"(b0), "r"(b1));
}

#define LDMX2T(b0, b1, addr) \
    asm volatile("ldmatrix.sync.aligned.m8n8.x2.trans.shared.b16 {%0,%1}, [%2];\n" \
                 : "=r"(b0), "=r"(b1) : "r"(addr))

#define LDMX4(r0, r1, r2, r3, addr) \
    asm volatile("ldmatrix.sync.aligned.m8n8.x4.shared.b16 {%0,%1,%2,%3}, [%4];\n" \
                 : "=r"(r0), "=r"(r1), "=r"(r2), "=r"(r3) : "r"(addr))

#define CP16(dst, src) \
    asm volatile("cp.async.cg.shared.global [%0], [%1], 16;\n" :: "r"(dst), "l"(src))
#define CP_COMMIT() asm volatile("cp.async.commit_group;\n")
#define CP_WAIT0()  asm volatile("cp.async.wait_group 0;\n")

__device__ __forceinline__ __nv_bfloat162 u2bf2(uint32_t u)
{
    return *reinterpret_cast<__nv_bfloat162*>(&u);
}

__device__ __forceinline__ uint32_t pk2(float v0, float v1)
{
    __nv_bfloat162 t;
    t.x = __float2bfloat16(v0);
    t.y = __float2bfloat16(v1);
    return *reinterpret_cast<uint32_t*>(&t);
}

// ============================================================
// Fused chain: v = lrelu(W0@in), x = W1@v, y0 = lrelu(Wsx@x + T + bs0)
// 512 threads = 16 warps, warp tile 32x32, grid (16,1,8).
// Single A panel, but issued for step p+1 BEFORE the epilogue of step p
// so the load hides under the epilogue. ph2 stores packed via shfl.
// ============================================================
#define BST 264
#define BBUF (CH * BST)
#define AST 200
#define APAN (64 * AST)

__global__ __launch_bounds__(512) void chain3_tc(
    const float* __restrict__ input,
    const bf16* __restrict__ W0, const bf16* __restrict__ W1,
    const bf16* __restrict__ Wsx,
    const float* __restrict__ bias0, const float* __restrict__ bias1,
    const float* __restrict__ bias2,
    const int* __restrict__ mask, const float* __restrict__ Tt,
    bf16* __restrict__ Xout, bf16* __restrict__ Y0i)
{
    extern __shared__ __align__(16) bf16 sm[];
    bf16* Bbuf0 = sm;
    bf16* Bbuf1 = sm + BBUF;
    bf16* As    = sm + 2 * BBUF;

    const int b   = blockIdx.z;
    const int n0  = blockIdx.x * 256;
    const int tid = threadIdx.x;
    const int lane = tid & 31;
    const int warp = tid >> 5;     // 0..15
    const int wm = warp >> 3;      // 0..1
    const int wn = warp & 7;       // 0..7
    const int tq = lane & 3;
    const int gq = lane >> 2;
    const int lg = lane >> 3;
    const int arow = (lg & 1) * 8 + (lane & 7);
    const int akoff = (lg >> 1) * 8;

    uint32_t s_as = (uint32_t)__cvta_generic_to_shared(As);

    auto issue = [&](int p) {
        int ph = p / 3, mc = p - ph * 3;
        const bf16* W = (ph == 0) ? W0 : (ph == 1 ? W1 : Wsx);
#pragma unroll
        for (int t = 0; t < 3; t++) {
            int idx = tid + t * 512;          // 1536 chunks exactly
            int i = idx / 24, c8 = (idx % 24) * 8;
            CP16(s_as + (uint32_t)(i * AST + c8) * 2,
                 W + (size_t)(mc * 64 + i) * CH + c8);
        }
    };

    // stage input tile fp32 -> bf16 into Bbuf0 (no sync needed yet)
    const float* inb = input + (size_t)b * CH * HWP;
    for (int idx = tid; idx < CH * 128; idx += 512) {
        int ch = idx >> 7, pu = idx & 127;
        float2 v = *(const float2*)(inb + (size_t)ch * HWP + n0 + 2 * pu);
        __nv_bfloat162 o;
        o.x = __float2bfloat16(v.x);
        o.y = __float2bfloat16(v.y);
        *(__nv_bfloat162*)(Bbuf0 + ch * BST + 2 * pu) = o;
    }
    issue(0);
    CP_COMMIT();

#pragma unroll 1
    for (int p = 0; p < 9; p++) {
        const int ph = p / 3;
        const int m0 = (p - ph * 3) * 64;
        const float* bias = (ph == 0) ? bias0 : (ph == 1 ? bias1 : bias2);
        bf16* Bsrc = (ph == 1) ? Bbuf1 : Bbuf0;
        bf16* Bdst = (ph == 0) ? Bbuf1 : Bbuf0;
        uint32_t s_bsrc = (uint32_t)__cvta_generic_to_shared(Bsrc);

        CP_WAIT0();
        __syncthreads();          // panel ready + prior epilogue smem writes done

        float c[2][4][4];
#pragma unroll
        for (int i = 0; i < 2; i++)
#pragma unroll
            for (int j = 0; j < 4; j++)
#pragma unroll
                for (int q = 0; q < 4; q++) c[i][j][q] = 0.f;

#pragma unroll
        for (int kt = 0; kt < CH; kt += 16) {
            uint32_t a[2][4];
#pragma unroll
            for (int mt = 0; mt < 2; mt++) {
                uint32_t aadr = s_as
                    + (uint32_t)((wm * 32 + mt * 16 + arow) * AST + kt + akoff) * 2;
                LDMX4(a[mt][0], a[mt][1], a[mt][2], a[mt][3], aadr);
            }
            uint32_t badr = s_bsrc
                + (uint32_t)((kt + (lane & 15)) * BST + wn * 32) * 2;
#pragma unroll
            for (int nt = 0; nt < 4; nt++) {
                uint32_t bf0, bf1;
                LDMX2T(bf0, bf1, badr + nt * 16);
                mma_bf16(c[0][nt], a[0], bf0, bf1);
                mma_bf16(c[1][nt], a[1], bf0, bf1);
            }
        }

        __syncthreads();          // all warps done reading As
        if (p < 8) { issue(p + 1); CP_COMMIT(); }   // load hides under epilogue

        // epilogue
#pragma unroll
        for (int mt = 0; mt < 2; mt++) {
#pragma unroll
            for (int half = 0; half < 2; half++) {
                int co = m0 + wm * 32 + mt * 16 + gq + half * 8;
                float bi = bias[co];
#pragma unroll
                for (int nt = 0; nt < 4; nt++) {
                    int ploc = wn * 32 + nt * 8 + tq * 2;
                    float v0 = c[mt][nt][half * 2 + 0] + bi;
                    float v1 = c[mt][nt][half * 2 + 1] + bi;
                    if (ph == 2) {
                        int pp = n0 + ploc;
                        int mk0 = mask[b * HWP + pp];
                        int mk1 = mask[b * HWP + pp + 1];
                        v0 += Tt[(b * MASKN + mk0) * CH + co];
                        v1 += Tt[(b * MASKN + mk1) * CH + co];
                        v0 = v0 > 0.f ? v0 : 0.1f * v0;
                        v1 = v1 > 0.f ? v1 : 0.1f * v1;
                        // pack channel pair (co, co+1) via shfl: 8-byte stores
                        uint32_t x = pk2(v0, v1);
                        uint32_t y = __shfl_down_sync(0xffffffffu, x, 4);
                        if ((gq & 1) == 0) {
                            uint32_t w0 = (x & 0xFFFFu) | (y << 16);
                            uint32_t w1 = (x >> 16) | (y & 0xFFFF0000u);
                            size_t w = ((size_t)b * (CH / 2) + (co >> 1)) * HWP + n0 + ploc;
                            *(uint2*)((uint32_t*)Y0i + w) = make_uint2(w0, w1);
                        }
                    } else {
                        if (ph == 0) {
                            v0 = v0 > 0.f ? v0 : 0.1f * v0;
                            v1 = v1 > 0.f ? v1 : 0.1f * v1;
                        }
                        __nv_bfloat162 o;
                        o.x = __float2bfloat16(v0);
                        o.y = __float2bfloat16(v1);
                        *(__nv_bfloat162*)(Bdst + co * BST + ploc) = o;
                        if (ph == 1)
                            *(__nv_bfloat162*)(Xout + ((size_t)b * CH + co) * HWP + n0 + ploc) = o;
                    }
                }
            }
        }
    }
}

// ============================================================
// FINAL 1x1 conv GEMM: BK=32 (6 pipeline steps instead of 12).
// Gate folded into A; fp32 out + residual.
// ============================================================
__global__ __launch_bounds__(256) void gemm_final_tc(
    const bf16* __restrict__ X, const bf16* __restrict__ Wb,
    const float* __restrict__ bias, float* __restrict__ Y,
    const float* __restrict__ gate, const float* __restrict__ resid)
{
    __shared__ __align__(16) bf16 As[2][64][40];    // 40h = 80B stride
    __shared__ __align__(16) bf16 Bs[2][32][264];
    __shared__ float sgate[CH];

    const int b   = blockIdx.z;
    const int m0  = blockIdx.y * 64;
    const int n0  = blockIdx.x * 256;
    const int tid = threadIdx.x;
    const int lane = tid & 31;
    const int warp = tid >> 5;
    const int wm = warp >> 2;
    const int wn = warp & 3;
    const int tq = lane & 3;
    const int gq = lane >> 2;
    const int lg = lane >> 3;
    const int arow = (lg & 1) * 8 + (lane & 7);
    const int akoff = (lg >> 1) * 8;

    const bf16* Xb = X + (size_t)b * CH * HWP;

    if (tid < CH) sgate[tid] = gate[b * CH + tid];
    __syncthreads();

    uint32_t s_as = (uint32_t)__cvta_generic_to_shared(&As[0][0][0]);
    uint32_t s_bs = (uint32_t)__cvta_generic_to_shared(&Bs[0][0][0]);

    float c[2][8][4];
#pragma unroll
    for (int i = 0; i < 2; i++)
#pragma unroll
        for (int j = 0; j < 8; j++)
#pragma unroll
            for (int q = 0; q < 4; q++) c[i][j][q] = 0.f;

    auto issue = [&](int kt, int st) {
        // gated A: 64 x 32, one uint4 per thread
        {
            int co = tid >> 2, h8 = (tid & 3) * 8;
            const bf16* src = Wb + (size_t)(m0 + co) * CH + kt + h8;
            bf16 tmp[8];
            *(uint4*)tmp = *(const uint4*)src;
            bf16 dst8[8];
#pragma unroll
            for (int i = 0; i < 8; i++)
                dst8[i] = __float2bfloat16(__bfloat162float(tmp[i]) * sgate[kt + h8 + i]);
            *(uint4*)&As[st][co][h8] = *(uint4*)dst8;
        }
        // B: 32 x 256, 1024 chunks
#pragma unroll
        for (int t = 0; t < 4; t++) {
            int idx = tid + t * 256;
            int k = idx >> 5, q = idx & 31;
            CP16(s_bs + (uint32_t)(st * 8448 + k * 264 + q * 8) * 2,
                 Xb + (size_t)(kt + k) * HWP + n0 + q * 8);
        }
    };

    issue(0, 0);
    CP_COMMIT();

    for (int step = 0; step < 6; step++) {
        CP_WAIT0();
        __syncthreads();
        if (step < 5) { issue((step + 1) * 32, (step + 1) & 1); CP_COMMIT(); }

        uint32_t sAc = s_as + (step & 1) * 2560 * 2;
        uint32_t sBc = s_bs + (step & 1) * 8448 * 2;

#pragma unroll
        for (int ks = 0; ks < 32; ks += 16) {
            uint32_t a[2][4];
#pragma unroll
            for (int mt = 0; mt < 2; mt++) {
                uint32_t aadr = sAc
                    + (uint32_t)((wm * 32 + mt * 16 + arow) * 40 + ks + akoff) * 2;
                LDMX4(a[mt][0], a[mt][1], a[mt][2], a[mt][3], aadr);
            }
            uint32_t badr = sBc
                + (uint32_t)((ks + (lane & 15)) * 264 + wn * 64) * 2;
#pragma unroll
            for (int nt = 0; nt < 8; nt++) {
                uint32_t b0, b1;
                LDMX2T(b0, b1, badr + nt * 16);
                mma_bf16(c[0][nt], a[0], b0, b1);
                mma_bf16(c[1][nt], a[1], b0, b1);
            }
        }
    }

#pragma unroll
    for (int mt = 0; mt < 2; mt++) {
#pragma unroll
        for (int half = 0; half < 2; half++) {
            int co = m0 + wm * 32 + mt * 16 + gq + half * 8;
            float bi = bias[co];
#pragma unroll
            for (int nt = 0; nt < 8; nt++) {
                int p = n0 + wn * 64 + nt * 8 + tq * 2;
                size_t off = ((size_t)b * CH + co) * HWP + p;
                float v0 = c[mt][nt][half * 2 + 0] + bi + resid[off];
                float v1 = c[mt][nt][half * 2 + 1] + bi + resid[off + 1];
                *(float2*)(Y + off) = make_float2(v0, v1);
            }
        }
    }
}

// ============================================================
// 3x3 conv, bf16 TC, channel-pair interleaved B, ldmatrix A.
// 128 threads = 4 warps, warp tile 64x64, 2 CTAs/SM. (unchanged)
// ============================================================
#define PSTW 440
#define PSTAGEW (8 * PSTW)
__global__ __launch_bounds__(128, 2) void conv3x3_tc(
    const bf16* __restrict__ Y0i, const bf16* __restrict__ Wr,
    const float* __restrict__ bias, bf16* __restrict__ Y)
{
    extern __shared__ __align__(16) bf16 smem[];
    bf16* Asb = smem;
    uint32_t* Psb = (uint32_t*)(smem + 2 * 13824);

    const int b    = blockIdx.z;
    const int m0   = blockIdx.y * 64;
    const int tile = blockIdx.x;
    const int row0 = tile * 4;
    const int n0   = tile * 256;
    const int tid  = threadIdx.x;
    const int lane = tid & 31;
    const int wn   = tid >> 5;
    const int tq = lane & 3;
    const int gq = lane >> 2;
    const int lg = lane >> 3;
    const int arow = (lg & 1) * 8 + (lane & 7);
    const int akoff = (lg >> 1) * 8;

    const uint32_t* Xw = (const uint32_t*)Y0i + (size_t)b * (CH / 2) * HWP;

    for (int i = tid; i < 2 * PSTAGEW; i += 128) Psb[i] = 0u;
    __syncthreads();

    uint32_t s_as = (uint32_t)__cvta_generic_to_shared(Asb);
    uint32_t s_ps = (uint32_t)__cvta_generic_to_shared(Psb);

    float c[4][8][4];
#pragma unroll
    for (int i = 0; i < 4; i++)
#pragma unroll
        for (int j = 0; j < 8; j++)
#pragma unroll
            for (int q = 0; q < 4; q++) c[i][j][q] = 0.f;

    auto issue = [&](int kt, int st) {
        uint32_t ab = s_as + st * (13824 * 2);
#pragma unroll
        for (int t = 0; t < 9; t++) {
            int idx = tid + t * 128;
            int r = idx >> 7;
            int rem = idx & 127;
            int co = rem >> 1, h8 = (rem & 1) * 8;
            CP16(ab + (uint32_t)((r * 64 + co) * 24 + h8) * 2,
                 Wr + ((size_t)r * CH + m0 + co) * CH + kt + h8);
        }
        uint32_t pb = s_ps + st * (PSTAGEW * 4);
        const int cp0 = kt >> 1;
#pragma unroll
        for (int t = 0; t < 6; t++) {
            int idx = tid + t * 128;
            int m = idx / 96;
            int rem = idx - m * 96;
            int rr = rem >> 4;
            int q  = rem & 15;
            int hh = row0 + rr - 1;
            if (hh >= 0 && hh < 64) {
                CP16(pb + (uint32_t)(m * PSTW + rr * 72 + 8 + q * 4) * 4,
                     Xw + (size_t)(cp0 + m) * HWP + hh * 64 + q * 4);
            }
        }
    };

    issue(0, 0);
    CP_COMMIT();

    for (int step = 0; step < 12; step++) {
        CP_WAIT0();
        __syncthreads();
        if (step < 11) { issue((step + 1) * 16, (step + 1) & 1); CP_COMMIT(); }

        uint32_t sAc = s_as + (step & 1) * (13824 * 2);
        const uint32_t* Pw = Psb + (step & 1) * PSTAGEW;

#pragma unroll 1
        for (int r = 0; r < 9; r++) {
            const int di = r / 3, dj = r - (r / 3) * 3;

            uint32_t a[4][4];
#pragma unroll
            for (int mt = 0; mt < 4; mt++) {
                uint32_t aadr = sAc
                    + (uint32_t)((r * 64 + mt * 16 + arow) * 24 + akoff) * 2;
                LDMX4(a[mt][0], a[mt][1], a[mt][2], a[mt][3], aadr);
            }
            const uint32_t* pr0 = Pw + tq * PSTW + (wn + di) * 72 + gq + dj + 7;
            const uint32_t* pr1 = pr0 + 4 * PSTW;
#pragma unroll
            for (int nt = 0; nt < 8; nt++) {
                uint32_t b0 = pr0[nt * 8];
                uint32_t b1 = pr1[nt * 8];
#pragma unroll
                for (int mt = 0; mt < 4; mt++)
                    mma_bf16(c[mt][nt], a[mt], b0, b1);
            }
        }
    }

#pragma unroll
    for (int mt = 0; mt < 4; mt++) {
#pragma unroll
        for (int half = 0; half < 2; half++) {
            int co = m0 + mt * 16 + gq + half * 8;
            float bi = bias[co];
#pragma unroll
            for (int nt = 0; nt < 8; nt++) {
                int p = n0 + wn * 64 + nt * 8 + tq * 2;
                float v0 = c[mt][nt][half * 2 + 0] + bi;
                float v1 = c[mt][nt][half * 2 + 1] + bi;
                v0 = v0 > 0.f ? v0 : 0.1f * v0;
                v1 = v1 > 0.f ? v1 : 0.1f * v1;
                __nv_bfloat162 o;
                o.x = __float2bfloat16(v0);
                o.y = __float2bfloat16(v1);
                *(__nv_bfloat162*)&Y[((size_t)b * CH + co) * HWP + p] = o;
            }
        }
    }
}

// ============================================================
// prep: convert weights to bf16 (+ reorder ws1 -> [r][co][ci])
// ============================================================
__global__ void prep_weights(
    const float* __restrict__ w0, const float* __restrict__ w1,
    const float* __restrict__ ws0, const float* __restrict__ ws1,
    const float* __restrict__ wo,
    bf16* __restrict__ w0b, bf16* __restrict__ w1b,
    bf16* __restrict__ wsxb, bf16* __restrict__ wob,
    bf16* __restrict__ wrb)
{
    const int S = CH * CH;
    int idx = blockIdx.x * 256 + threadIdx.x;
    if (idx < S) {
        w0b[idx] = __float2bfloat16(w0[idx]);
    } else if (idx < 2 * S) {
        int i = idx - S;
        w1b[i] = __float2bfloat16(w1[i]);
    } else if (idx < 3 * S) {
        int i = idx - 2 * S;
        int co = i / CH, ci = i % CH;
        wsxb[i] = __float2bfloat16(ws0[(size_t)co * (2 * CH) + ci]);
    } else if (idx < 4 * S) {
        int i = idx - 3 * S;
        wob[i] = __float2bfloat16(wo[i]);
    } else if (idx < 4 * S + 9 * S) {
        int i = idx - 4 * S;
        int ci = i % CH;
        int co = (i / CH) % CH;
        int r  = i / S;
        wrb[i] = __float2bfloat16(ws1[((size_t)co * CH + ci) * 9 + r]);
    }
}

// ============================================================
// T[b,m,co] = sum_ci ws0[co, 192+ci] * list_center[b,m,ci]
// ============================================================
__global__ __launch_bounds__(256) void tgen_kernel(
    const float* __restrict__ lc, const float* __restrict__ ws0,
    float* __restrict__ T)
{
    __shared__ float cvec[CH];
    const int bm = blockIdx.x;
    const int cg = blockIdx.y;
    const int tid = threadIdx.x;
    if (tid < CH) cvec[tid] = lc[(size_t)bm * CH + tid];
    __syncthreads();
    const int warp = tid >> 5, lane = tid & 31;
    const int co0 = cg * 32 + warp * 4;
#pragma unroll
    for (int q = 0; q < 4; q++) {
        const float* w = ws0 + (size_t)(co0 + q) * (2 * CH) + CH;
        float s = 0.f;
#pragma unroll
        for (int j = lane; j < CH; j += 32) s = fmaf(w[j], cvec[j], s);
#pragma unroll
        for (int o = 16; o; o >>= 1) s += __shfl_xor_sync(0xffffffffu, s, o);
        if (lane == 0) T[bm * CH + co0 + q] = s;
    }
}

// ============================================================
// Fused depthwise-3x3 (k_sp) + dynamic conv + mean reduce.
// bf16x2 HFMA2 arithmetic. (unchanged R11)
// ============================================================
#define DROW 68
__global__ __launch_bounds__(256) void dyn_kernel(
    const bf16* __restrict__ Y1, const bf16* __restrict__ Xf,
    const float* __restrict__ ws2, const float* __restrict__ bs2,
    bf16* __restrict__ Out, float* __restrict__ Mean)
{
    __shared__ __align__(4) bf16 sy[66 * DROW];
    __shared__ __align__(4) bf16 sx[66 * DROW];
    __shared__ __nv_bfloat162 taps2[81];
    __shared__ __nv_bfloat162 tb2[9];
    __shared__ float red[256];

    const int c = blockIdx.x;
    const int b = blockIdx.y;
    const int tid = threadIdx.x;

    const bf16* y1p = Y1 + ((size_t)b * CH + c) * HWP;
    const bf16* xp  = Xf + ((size_t)b * CH + c) * HWP;

    for (int idx = tid; idx < 66 * DROW; idx += 256) {
        int row = idx / DROW;
        int col = idx - row * DROW;
        int hh = row - 1, ww = col - 1;
        bool ok = (hh >= 0 && hh < 64 && ww >= 0 && ww < 64);
        sy[idx] = ok ? y1p[hh * 64 + ww] : __float2bfloat16(0.f);
        sx[idx] = ok ? xp[hh * 64 + ww] : __float2bfloat16(0.f);
    }
    if (tid < 81) {
        bf16 h = __float2bfloat16(ws2[c * 81 + tid]);
        taps2[tid] = __nv_bfloat162(h, h);
    }
    if (tid < 9) {
        bf16 h = __float2bfloat16(bs2[c * 9 + tid]);
        tb2[tid] = __nv_bfloat162(h, h);
    }
    __syncthreads();

    float sum = 0.f;
    for (int pp2 = tid; pp2 < 2048; pp2 += 256) {
        const int hq = pp2 >> 5;
        const int c0 = (pp2 & 31) * 2;
        const int w0i = c0 >> 1;

        __nv_bfloat162 yp[9], xpr[9];
#pragma unroll
        for (int di = 0; di < 3; di++) {
            const uint32_t* ry = (const uint32_t*)(sy + (hq + di) * DROW);
            const uint32_t* rx = (const uint32_t*)(sx + (hq + di) * DROW);
            uint32_t ya = ry[w0i], yb = ry[w0i + 1];
            uint32_t xa = rx[w0i], xb = rx[w0i + 1];
            yp[di * 3 + 0] = u2bf2(ya);
            yp[di * 3 + 1] = u2bf2((ya >> 16) | (yb << 16));
            yp[di * 3 + 2] = u2bf2(yb);
            xpr[di * 3 + 0] = u2bf2(xa);
            xpr[di * 3 + 1] = u2bf2((xa >> 16) | (xb << 16));
            xpr[di * 3 + 2] = u2bf2(xb);
        }

        __nv_bfloat162 o = __nv_bfloat162(__float2bfloat16(0.f), __float2bfloat16(0.f));
#pragma unroll
        for (int kk = 0; kk < 9; kk++) {
            __nv_bfloat162 ks = tb2[kk];
#pragma unroll
            for (int r = 0; r < 9; r++)
                ks = __hfma2(yp[r], taps2[kk * 9 + r], ks);
            o = __hfma2(xpr[kk], ks, o);
        }

        int p0 = hq * 64 + c0;
        *(__nv_bfloat162*)(&Out[((size_t)b * CH + c) * HWP + p0]) = o;
        sum += __bfloat162float(o.x) + __bfloat162float(o.y);
    }
    red[tid] = sum;
    __syncthreads();
    for (int s = 128; s > 0; s >>= 1) {
        if (tid < s) red[tid] += red[tid + s];
        __syncthreads();
    }
    if (tid == 0) Mean[b * CH + c] = red[0] * (1.f / HWP);
}

// ============================================================
// SE gate (one block per batch element)
// ============================================================
__global__ __launch_bounds__(192) void se_kernel(
    const float* __restrict__ Mean,
    const float* __restrict__ wc0, const float* __restrict__ bc0,
    const float* __restrict__ wc1, const float* __restrict__ bc1,
    float* __restrict__ Gate)
{
    __shared__ float m[CH];
    __shared__ float hbuf[CH];
    const int b = blockIdx.x;
    const int i = threadIdx.x;
    m[i] = Mean[b * CH + i];
    __syncthreads();
    float s = bc0[i];
    const float* w = wc0 + (size_t)i * CH;
#pragma unroll 8
    for (int j = 0; j < CH; j++) s = fmaf(w[j], m[j], s);
    hbuf[i] = s > 0.f ? s : 0.1f * s;
    __syncthreads();
    float s2 = bc1[i];
    const float* w2 = wc1 + (size_t)i * CH;
#pragma unroll 8
    for (int j = 0; j < CH; j++) s2 = fmaf(w2[j], hbuf[j], s2);
    Gate[b * CH + i] = 1.f / (1.f + expf(-s2));
}

extern "C" void kernel_launch(void* const* d_in, const int* in_sizes, int n_in,
                              void* d_out, int out_size)
{
    const float* input = (const float*)d_in[0];
    const float* lc    = (const float*)d_in[1];
    const int*   mask  = (const int*)d_in[2];
    const float* w0  = (const float*)d_in[3];
    const float* b0  = (const float*)d_in[4];
    const float* w1  = (const float*)d_in[5];
    const float* b1  = (const float*)d_in[6];
    const float* ws0 = (const float*)d_in[7];
    const float* bs0 = (const float*)d_in[8];
    const float* ws1 = (const float*)d_in[9];
    const float* bs1 = (const float*)d_in[10];
    const float* ws2 = (const float*)d_in[11];
    const float* bs2 = (const float*)d_in[12];
    const float* wc0 = (const float*)d_in[13];
    const float* bc0 = (const float*)d_in[14];
    const float* wc1 = (const float*)d_in[15];
    const float* bc1 = (const float*)d_in[16];
    const float* wo  = (const float*)d_in[17];
    const float* bo  = (const float*)d_in[18];
    float* out = (float*)d_out;

    bf16 *pb0, *pb1, *pb2, *pb3, *pw0b, *pw1b, *pwsxb, *pwob, *pwrb;
    float *pT, *pMean, *pGate;
    cudaGetSymbolAddress((void**)&pb0, g_b0);
    cudaGetSymbolAddress((void**)&pb1, g_b1);
    cudaGetSymbolAddress((void**)&pb2, g_b2);
    cudaGetSymbolAddress((void**)&pb3, g_b3);
    cudaGetSymbolAddress((void**)&pw0b, g_w0b);
    cudaGetSymbolAddress((void**)&pw1b, g_w1b);
    cudaGetSymbolAddress((void**)&pwsxb, g_wsxb);
    cudaGetSymbolAddress((void**)&pwob, g_wob);
    cudaGetSymbolAddress((void**)&pwrb, g_wrb);
    cudaGetSymbolAddress((void**)&pT, g_T);
    cudaGetSymbolAddress((void**)&pMean, g_mean);
    cudaGetSymbolAddress((void**)&pGate, g_gate);

    const int conv_smem  = 2 * 13824 * 2 + 2 * PSTAGEW * 4;        // 83,456 B
    const int chain_smem = (2 * BBUF + APAN) * 2;                  // 228,352 B
    cudaFuncSetAttribute(conv3x3_tc,
                         cudaFuncAttributeMaxDynamicSharedMemorySize, conv_smem);
    cudaFuncSetAttribute(chain3_tc,
                         cudaFuncAttributeMaxDynamicSharedMemorySize, chain_smem);

    // 0) prep weights (bf16 + reorder)
    prep_weights<<<(13 * CH * CH + 255) / 256, 256>>>(
        w0, w1, ws0, ws1, wo, pw0b, pw1b, pwsxb, pwob, pwrb);
    // 1) T table
    tgen_kernel<<<dim3(BSZ * MASKN, 6), 256>>>(lc, ws0, pT);
    // 2) fused chain: v -> x -> y0  (x to g_b1, y0 interleaved to g_b2)
    chain3_tc<<<dim3(16, 1, 8), 512, chain_smem>>>(
        input, pw0b, pw1b, pwsxb, b0, b1, bs0, mask, pT, pb1, pb2);
    // 3) y1 = lrelu(conv3x3(y0, ws1, bs1))
    conv3x3_tc<<<dim3(16, 3, 8), 128, conv_smem>>>(pb2, pwrb, bs1, pb3);
    // 4) out_feat = dynamic_conv(x, depthwise(y1)) ; per-(b,c) mean
    dyn_kernel<<<dim3(CH, BSZ), 256>>>(pb3, pb1, ws2, bs2, pb0, pMean);
    // 5) gate
    se_kernel<<<BSZ, 192>>>(pMean, wc0, bc0, wc1, bc1, pGate);
    // 6) out = conv1x1(gate*out_feat, wo, bo) + input
    gemm_final_tc<<<dim3(16, 3, 8), 256>>>(
        pb0, pwob, bo, out, pGate, input);
}

// round 13
// speedup vs baseline: 1.1488x; 1.0195x over previous
#include <cuda_runtime.h>
#include <cuda_bf16.h>
#include <math.h>
#include <stdint.h>

#define BSZ 8
#define CH 192
#define HWP 4096
#define MASKN 16

typedef __nv_bfloat16 bf16;

// ---- scratch (static device globals) ----
__device__ bf16 g_b0[BSZ * CH * HWP];    // dyn-conv output
__device__ bf16 g_b1[BSZ * CH * HWP];    // x
__device__ bf16 g_b2[BSZ * CH * HWP];    // y0 (channel-pair interleaved!)
__device__ bf16 g_b3[BSZ * CH * HWP];    // y1
__device__ bf16 g_w0b[CH * CH];
__device__ bf16 g_w1b[CH * CH];
__device__ bf16 g_wsxb[CH * CH];         // x-half of ws0
__device__ bf16 g_wob[CH * CH];
__device__ bf16 g_wrb[9 * CH * CH];      // reordered ws1: [r][co][ci]
__device__ float g_T[BSZ * MASKN * CH];
__device__ float g_mean[BSZ * CH];
__device__ float g_gate[BSZ * CH];

// ---- bf16 mma m16n8k16 (row.col), fp32 accumulate ----
__device__ __forceinline__ void mma_bf16(float* c, const uint32_t* a, uint32_t b0, uint32_t b1)
{
    asm("mma.sync.aligned.m16n8k16.row.col.f32.bf16.bf16.f32 "
        "{%0,%1,%2,%3}, {%4,%5,%6,%7}, {%8,%9}, {%0,%1,%2,%3};\n"
        : "+f"(c[0]), "+f"(c[1]), "+f"(c[2]), "+f"(c[3])
        : "r"(a[0]), "r"(a[1]), "r"(a[2]), "r"(a[3]), "r"(b0), "r"(b1));
}

#define LDMX2T(b0, b1, addr) \
    asm volatile("ldmatrix.sync.aligned.m8n8.x2.trans.shared.b16 {%0,%1}, [%2];\n" \
                 : "=r"(b0), "=r"(b1) : "r"(addr))

#define LDMX4(r0, r1, r2, r3, addr) \
    asm volatile("ldmatrix.sync.aligned.m8n8.x4.shared.b16 {%0,%1,%2,%3}, [%4];\n" \
                 : "=r"(r0), "=r"(r1), "=r"(r2), "=r"(r3) : "r"(addr))

#define CP16(dst, src) \
    asm volatile("cp.async.cg.shared.global [%0], [%1], 16;\n" :: "r"(dst), "l"(src))
#define CP_COMMIT() asm volatile("cp.async.commit_group;\n")
#define CP_WAIT0()  asm volatile("cp.async.wait_group 0;\n")

__device__ __forceinline__ __nv_bfloat162 u2bf2(uint32_t u)
{
    return *reinterpret_cast<__nv_bfloat162*>(&u);
}

__device__ __forceinline__ uint32_t pk2(float v0, float v1)
{
    __nv_bfloat162 t;
    t.x = __float2bfloat16(v0);
    t.y = __float2bfloat16(v1);
    return *reinterpret_cast<uint32_t*>(&t);
}

// ============================================================
// Fused chain: v = lrelu(W0@in), x = W1@v, y0 = lrelu(Wsx@x + T + bs0)
// 512 threads = 16 warps, warp tile 32x32, grid (16,1,8).
// Panel p+1 load issued before epilogue of step p (hides under it).
// ph2 stores packed via shfl into 8-byte stores. (unchanged R12)
// ============================================================
#define BST 264
#define BBUF (CH * BST)
#define AST 200
#define APAN (64 * AST)

__global__ __launch_bounds__(512) void chain3_tc(
    const float* __restrict__ input,
    const bf16* __restrict__ W0, const bf16* __restrict__ W1,
    const bf16* __restrict__ Wsx,
    const float* __restrict__ bias0, const float* __restrict__ bias1,
    const float* __restrict__ bias2,
    const int* __restrict__ mask, const float* __restrict__ Tt,
    bf16* __restrict__ Xout, bf16* __restrict__ Y0i)
{
    extern __shared__ __align__(16) bf16 sm[];
    bf16* Bbuf0 = sm;
    bf16* Bbuf1 = sm + BBUF;
    bf16* As    = sm + 2 * BBUF;

    const int b   = blockIdx.z;
    const int n0  = blockIdx.x * 256;
    const int tid = threadIdx.x;
    const int lane = tid & 31;
    const int warp = tid >> 5;     // 0..15
    const int wm = warp >> 3;      // 0..1
    const int wn = warp & 7;       // 0..7
    const int tq = lane & 3;
    const int gq = lane >> 2;
    const int lg = lane >> 3;
    const int arow = (lg & 1) * 8 + (lane & 7);
    const int akoff = (lg >> 1) * 8;

    uint32_t s_as = (uint32_t)__cvta_generic_to_shared(As);

    auto issue = [&](int p) {
        int ph = p / 3, mc = p - ph * 3;
        const bf16* W = (ph == 0) ? W0 : (ph == 1 ? W1 : Wsx);
#pragma unroll
        for (int t = 0; t < 3; t++) {
            int idx = tid + t * 512;          // 1536 chunks exactly
            int i = idx / 24, c8 = (idx % 24) * 8;
            CP16(s_as + (uint32_t)(i * AST + c8) * 2,
                 W + (size_t)(mc * 64 + i) * CH + c8);
        }
    };

    const float* inb = input + (size_t)b * CH * HWP;
    for (int idx = tid; idx < CH * 128; idx += 512) {
        int ch = idx >> 7, pu = idx & 127;
        float2 v = *(const float2*)(inb + (size_t)ch * HWP + n0 + 2 * pu);
        __nv_bfloat162 o;
        o.x = __float2bfloat16(v.x);
        o.y = __float2bfloat16(v.y);
        *(__nv_bfloat162*)(Bbuf0 + ch * BST + 2 * pu) = o;
    }
    issue(0);
    CP_COMMIT();

#pragma unroll 1
    for (int p = 0; p < 9; p++) {
        const int ph = p / 3;
        const int m0 = (p - ph * 3) * 64;
        const float* bias = (ph == 0) ? bias0 : (ph == 1 ? bias1 : bias2);
        bf16* Bsrc = (ph == 1) ? Bbuf1 : Bbuf0;
        bf16* Bdst = (ph == 0) ? Bbuf1 : Bbuf0;
        uint32_t s_bsrc = (uint32_t)__cvta_generic_to_shared(Bsrc);

        CP_WAIT0();
        __syncthreads();

        float c[2][4][4];
#pragma unroll
        for (int i = 0; i < 2; i++)
#pragma unroll
            for (int j = 0; j < 4; j++)
#pragma unroll
                for (int q = 0; q < 4; q++) c[i][j][q] = 0.f;

#pragma unroll
        for (int kt = 0; kt < CH; kt += 16) {
            uint32_t a[2][4];
#pragma unroll
            for (int mt = 0; mt < 2; mt++) {
                uint32_t aadr = s_as
                    + (uint32_t)((wm * 32 + mt * 16 + arow) * AST + kt + akoff) * 2;
                LDMX4(a[mt][0], a[mt][1], a[mt][2], a[mt][3], aadr);
            }
            uint32_t badr = s_bsrc
                + (uint32_t)((kt + (lane & 15)) * BST + wn * 32) * 2;
#pragma unroll
            for (int nt = 0; nt < 4; nt++) {
                uint32_t bf0, bf1;
                LDMX2T(bf0, bf1, badr + nt * 16);
                mma_bf16(c[0][nt], a[0], bf0, bf1);
                mma_bf16(c[1][nt], a[1], bf0, bf1);
            }
        }

        __syncthreads();
        if (p < 8) { issue(p + 1); CP_COMMIT(); }

        // epilogue
#pragma unroll
        for (int mt = 0; mt < 2; mt++) {
#pragma unroll
            for (int half = 0; half < 2; half++) {
                int co = m0 + wm * 32 + mt * 16 + gq + half * 8;
                float bi = bias[co];
#pragma unroll
                for (int nt = 0; nt < 4; nt++) {
                    int ploc = wn * 32 + nt * 8 + tq * 2;
                    float v0 = c[mt][nt][half * 2 + 0] + bi;
                    float v1 = c[mt][nt][half * 2 + 1] + bi;
                    if (ph == 2) {
                        int pp = n0 + ploc;
                        int mk0 = mask[b * HWP + pp];
                        int mk1 = mask[b * HWP + pp + 1];
                        v0 += Tt[(b * MASKN + mk0) * CH + co];
                        v1 += Tt[(b * MASKN + mk1) * CH + co];
                        v0 = v0 > 0.f ? v0 : 0.1f * v0;
                        v1 = v1 > 0.f ? v1 : 0.1f * v1;
                        uint32_t x = pk2(v0, v1);
                        uint32_t y = __shfl_down_sync(0xffffffffu, x, 4);
                        if ((gq & 1) == 0) {
                            uint32_t w0 = (x & 0xFFFFu) | (y << 16);
                            uint32_t w1 = (x >> 16) | (y & 0xFFFF0000u);
                            size_t w = ((size_t)b * (CH / 2) + (co >> 1)) * HWP + n0 + ploc;
                            *(uint2*)((uint32_t*)Y0i + w) = make_uint2(w0, w1);
                        }
                    } else {
                        if (ph == 0) {
                            v0 = v0 > 0.f ? v0 : 0.1f * v0;
                            v1 = v1 > 0.f ? v1 : 0.1f * v1;
                        }
                        __nv_bfloat162 o;
                        o.x = __float2bfloat16(v0);
                        o.y = __float2bfloat16(v1);
                        *(__nv_bfloat162*)(Bdst + co * BST + ploc) = o;
                        if (ph == 1)
                            *(__nv_bfloat162*)(Xout + ((size_t)b * CH + co) * HWP + n0 + ploc) = o;
                    }
                }
            }
        }
    }
}

// ============================================================
// FINAL 1x1 conv GEMM: BK=32, 6 pipeline steps. (unchanged R12)
// ============================================================
__global__ __launch_bounds__(256) void gemm_final_tc(
    const bf16* __restrict__ X, const bf16* __restrict__ Wb,
    const float* __restrict__ bias, float* __restrict__ Y,
    const float* __restrict__ gate, const float* __restrict__ resid)
{
    __shared__ __align__(16) bf16 As[2][64][40];
    __shared__ __align__(16) bf16 Bs[2][32][264];
    __shared__ float sgate[CH];

    const int b   = blockIdx.z;
    const int m0  = blockIdx.y * 64;
    const int n0  = blockIdx.x * 256;
    const int tid = threadIdx.x;
    const int lane = tid & 31;
    const int warp = tid >> 5;
    const int wm = warp >> 2;
    const int wn = warp & 3;
    const int tq = lane & 3;
    const int gq = lane >> 2;
    const int lg = lane >> 3;
    const int arow = (lg & 1) * 8 + (lane & 7);
    const int akoff = (lg >> 1) * 8;

    const bf16* Xb = X + (size_t)b * CH * HWP;

    if (tid < CH) sgate[tid] = gate[b * CH + tid];
    __syncthreads();

    uint32_t s_as = (uint32_t)__cvta_generic_to_shared(&As[0][0][0]);
    uint32_t s_bs = (uint32_t)__cvta_generic_to_shared(&Bs[0][0][0]);

    float c[2][8][4];
#pragma unroll
    for (int i = 0; i < 2; i++)
#pragma unroll
        for (int j = 0; j < 8; j++)
#pragma unroll
            for (int q = 0; q < 4; q++) c[i][j][q] = 0.f;

    auto issue = [&](int kt, int st) {
        {
            int co = tid >> 2, h8 = (tid & 3) * 8;
            const bf16* src = Wb + (size_t)(m0 + co) * CH + kt + h8;
            bf16 tmp[8];
            *(uint4*)tmp = *(const uint4*)src;
            bf16 dst8[8];
#pragma unroll
            for (int i = 0; i < 8; i++)
                dst8[i] = __float2bfloat16(__bfloat162float(tmp[i]) * sgate[kt + h8 + i]);
            *(uint4*)&As[st][co][h8] = *(uint4*)dst8;
        }
#pragma unroll
        for (int t = 0; t < 4; t++) {
            int idx = tid + t * 256;
            int k = idx >> 5, q = idx & 31;
            CP16(s_bs + (uint32_t)(st * 8448 + k * 264 + q * 8) * 2,
                 Xb + (size_t)(kt + k) * HWP + n0 + q * 8);
        }
    };

    issue(0, 0);
    CP_COMMIT();

    for (int step = 0; step < 6; step++) {
        CP_WAIT0();
        __syncthreads();
        if (step < 5) { issue((step + 1) * 32, (step + 1) & 1); CP_COMMIT(); }

        uint32_t sAc = s_as + (step & 1) * 2560 * 2;
        uint32_t sBc = s_bs + (step & 1) * 8448 * 2;

#pragma unroll
        for (int ks = 0; ks < 32; ks += 16) {
            uint32_t a[2][4];
#pragma unroll
            for (int mt = 0; mt < 2; mt++) {
                uint32_t aadr = sAc
                    + (uint32_t)((wm * 32 + mt * 16 + arow) * 40 + ks + akoff) * 2;
                LDMX4(a[mt][0], a[mt][1], a[mt][2], a[mt][3], aadr);
            }
            uint32_t badr = sBc
                + (uint32_t)((ks + (lane & 15)) * 264 + wn * 64) * 2;
#pragma unroll
            for (int nt = 0; nt < 8; nt++) {
                uint32_t b0, b1;
                LDMX2T(b0, b1, badr + nt * 16);
                mma_bf16(c[0][nt], a[0], b0, b1);
                mma_bf16(c[1][nt], a[1], b0, b1);
            }
        }
    }

#pragma unroll
    for (int mt = 0; mt < 2; mt++) {
#pragma unroll
        for (int half = 0; half < 2; half++) {
            int co = m0 + wm * 32 + mt * 16 + gq + half * 8;
            float bi = bias[co];
#pragma unroll
            for (int nt = 0; nt < 8; nt++) {
                int p = n0 + wn * 64 + nt * 8 + tq * 2;
                size_t off = ((size_t)b * CH + co) * HWP + p;
                float v0 = c[mt][nt][half * 2 + 0] + bi + resid[off];
                float v1 = c[mt][nt][half * 2 + 1] + bi + resid[off + 1];
                *(float2*)(Y + off) = make_float2(v0, v1);
            }
        }
    }
}

// ============================================================
// 3x3 conv, bf16 TC, channel-pair interleaved B, ldmatrix A.
// 128 threads = 4 warps, warp tile 64x64, 2 CTAs/SM.
// NEW: A fragments software-pipelined across taps (a0/a1 ping-pong,
// static parity via paired loop bodies) — tap r+1's LDMX4 burst
// overlaps tap r's 32 MMAs.
// ============================================================
#define PSTW 440
#define PSTAGEW (8 * PSTW)
__global__ __launch_bounds__(128, 2) void conv3x3_tc(
    const bf16* __restrict__ Y0i, const bf16* __restrict__ Wr,
    const float* __restrict__ bias, bf16* __restrict__ Y)
{
    extern __shared__ __align__(16) bf16 smem[];
    bf16* Asb = smem;
    uint32_t* Psb = (uint32_t*)(smem + 2 * 13824);

    const int b    = blockIdx.z;
    const int m0   = blockIdx.y * 64;
    const int tile = blockIdx.x;
    const int row0 = tile * 4;
    const int n0   = tile * 256;
    const int tid  = threadIdx.x;
    const int lane = tid & 31;
    const int wn   = tid >> 5;
    const int tq = lane & 3;
    const int gq = lane >> 2;
    const int lg = lane >> 3;
    const int arow = (lg & 1) * 8 + (lane & 7);
    const int akoff = (lg >> 1) * 8;

    const uint32_t* Xw = (const uint32_t*)Y0i + (size_t)b * (CH / 2) * HWP;

    for (int i = tid; i < 2 * PSTAGEW; i += 128) Psb[i] = 0u;
    __syncthreads();

    uint32_t s_as = (uint32_t)__cvta_generic_to_shared(Asb);
    uint32_t s_ps = (uint32_t)__cvta_generic_to_shared(Psb);

    float c[4][8][4];
#pragma unroll
    for (int i = 0; i < 4; i++)
#pragma unroll
        for (int j = 0; j < 8; j++)
#pragma unroll
            for (int q = 0; q < 4; q++) c[i][j][q] = 0.f;

    auto issue = [&](int kt, int st) {
        uint32_t ab = s_as + st * (13824 * 2);
#pragma unroll
        for (int t = 0; t < 9; t++) {
            int idx = tid + t * 128;
            int r = idx >> 7;
            int rem = idx & 127;
            int co = rem >> 1, h8 = (rem & 1) * 8;
            CP16(ab + (uint32_t)((r * 64 + co) * 24 + h8) * 2,
                 Wr + ((size_t)r * CH + m0 + co) * CH + kt + h8);
        }
        uint32_t pb = s_ps + st * (PSTAGEW * 4);
        const int cp0 = kt >> 1;
#pragma unroll
        for (int t = 0; t < 6; t++) {
            int idx = tid + t * 128;
            int m = idx / 96;
            int rem = idx - m * 96;
            int rr = rem >> 4;
            int q  = rem & 15;
            int hh = row0 + rr - 1;
            if (hh >= 0 && hh < 64) {
                CP16(pb + (uint32_t)(m * PSTW + rr * 72 + 8 + q * 4) * 4,
                     Xw + (size_t)(cp0 + m) * HWP + hh * 64 + q * 4);
            }
        }
    };

    issue(0, 0);
    CP_COMMIT();

    for (int step = 0; step < 12; step++) {
        CP_WAIT0();
        __syncthreads();
        if (step < 11) { issue((step + 1) * 16, (step + 1) & 1); CP_COMMIT(); }

        uint32_t sAc = s_as + (step & 1) * (13824 * 2);
        const uint32_t* Pw = Psb + (step & 1) * PSTAGEW;

        uint32_t a0[4][4], a1[4][4];

        auto lda = [&](uint32_t (&a)[4][4], int r) {
#pragma unroll
            for (int mt = 0; mt < 4; mt++) {
                uint32_t aadr = sAc
                    + (uint32_t)((r * 64 + mt * 16 + arow) * 24 + akoff) * 2;
                LDMX4(a[mt][0], a[mt][1], a[mt][2], a[mt][3], aadr);
            }
        };
        auto tap = [&](uint32_t (&a)[4][4], int r) {
            const int di = r / 3, dj = r - (r / 3) * 3;
            const uint32_t* pr0 = Pw + tq * PSTW + (wn + di) * 72 + gq + dj + 7;
            const uint32_t* pr1 = pr0 + 4 * PSTW;
#pragma unroll
            for (int nt = 0; nt < 8; nt++) {
                uint32_t b0 = pr0[nt * 8];
                uint32_t b1 = pr1[nt * 8];
#pragma unroll
                for (int mt = 0; mt < 4; mt++)
                    mma_bf16(c[mt][nt], a[mt], b0, b1);
            }
        };

        lda(a0, 0);
#pragma unroll 1
        for (int rr = 0; rr < 4; rr++) {
            lda(a1, 2 * rr + 1);      // prefetch odd tap
            tap(a0, 2 * rr);          // compute even tap
            lda(a0, 2 * rr + 2);      // prefetch next even tap (rr=3 -> tap 8)
            tap(a1, 2 * rr + 1);      // compute odd tap
        }
        tap(a0, 8);                   // tail tap, prefetched in rr=3
    }

#pragma unroll
    for (int mt = 0; mt < 4; mt++) {
#pragma unroll
        for (int half = 0; half < 2; half++) {
            int co = m0 + mt * 16 + gq + half * 8;
            float bi = bias[co];
#pragma unroll
            for (int nt = 0; nt < 8; nt++) {
                int p = n0 + wn * 64 + nt * 8 + tq * 2;
                float v0 = c[mt][nt][half * 2 + 0] + bi;
                float v1 = c[mt][nt][half * 2 + 1] + bi;
                v0 = v0 > 0.f ? v0 : 0.1f * v0;
                v1 = v1 > 0.f ? v1 : 0.1f * v1;
                __nv_bfloat162 o;
                o.x = __float2bfloat16(v0);
                o.y = __float2bfloat16(v1);
                *(__nv_bfloat162*)&Y[((size_t)b * CH + co) * HWP + p] = o;
            }
        }
    }
}

// ============================================================
// prep + tgen merged: one launch.
// blocks [0, NPREP): weight convert/reorder; [NPREP, NPREP+768): tgen.
// ============================================================
#define NPREP ((13 * CH * CH + 255) / 256)
__global__ __launch_bounds__(256) void prep_all(
    const float* __restrict__ w0, const float* __restrict__ w1,
    const float* __restrict__ ws0, const float* __restrict__ ws1,
    const float* __restrict__ wo, const float* __restrict__ lc,
    bf16* __restrict__ w0b, bf16* __restrict__ w1b,
    bf16* __restrict__ wsxb, bf16* __restrict__ wob,
    bf16* __restrict__ wrb, float* __restrict__ T)
{
    const int S = CH * CH;
    if (blockIdx.x < NPREP) {
        int idx = blockIdx.x * 256 + threadIdx.x;
        if (idx < S) {
            w0b[idx] = __float2bfloat16(w0[idx]);
        } else if (idx < 2 * S) {
            int i = idx - S;
            w1b[i] = __float2bfloat16(w1[i]);
        } else if (idx < 3 * S) {
            int i = idx - 2 * S;
            int co = i / CH, ci = i % CH;
            wsxb[i] = __float2bfloat16(ws0[(size_t)co * (2 * CH) + ci]);
        } else if (idx < 4 * S) {
            int i = idx - 3 * S;
            wob[i] = __float2bfloat16(wo[i]);
        } else if (idx < 13 * S) {
            int i = idx - 4 * S;
            int ci = i % CH;
            int co = (i / CH) % CH;
            int r  = i / S;
            wrb[i] = __float2bfloat16(ws1[((size_t)co * CH + ci) * 9 + r]);
        }
    } else {
        __shared__ float cvec[CH];
        int blk = blockIdx.x - NPREP;       // 0..767
        int bm = blk / 6, cg = blk - (blk / 6) * 6;
        const int tid = threadIdx.x;
        if (tid < CH) cvec[tid] = lc[(size_t)bm * CH + tid];
        __syncthreads();
        const int warp = tid >> 5, lane = tid & 31;
        const int co0 = cg * 32 + warp * 4;
#pragma unroll
        for (int q = 0; q < 4; q++) {
            const float* w = ws0 + (size_t)(co0 + q) * (2 * CH) + CH;
            float s = 0.f;
#pragma unroll
            for (int j = lane; j < CH; j += 32) s = fmaf(w[j], cvec[j], s);
#pragma unroll
            for (int o = 16; o; o >>= 1) s += __shfl_xor_sync(0xffffffffu, s, o);
            if (lane == 0) T[bm * CH + co0 + q] = s;
        }
    }
}

// ============================================================
// Fused depthwise-3x3 (k_sp) + dynamic conv + mean reduce.
// bf16x2 HFMA2 arithmetic. (unchanged R11)
// ============================================================
#define DROW 68
__global__ __launch_bounds__(256) void dyn_kernel(
    const bf16* __restrict__ Y1, const bf16* __restrict__ Xf,
    const float* __restrict__ ws2, const float* __restrict__ bs2,
    bf16* __restrict__ Out, float* __restrict__ Mean)
{
    __shared__ __align__(4) bf16 sy[66 * DROW];
    __shared__ __align__(4) bf16 sx[66 * DROW];
    __shared__ __nv_bfloat162 taps2[81];
    __shared__ __nv_bfloat162 tb2[9];
    __shared__ float red[256];

    const int c = blockIdx.x;
    const int b = blockIdx.y;
    const int tid = threadIdx.x;

    const bf16* y1p = Y1 + ((size_t)b * CH + c) * HWP;
    const bf16* xp  = Xf + ((size_t)b * CH + c) * HWP;

    for (int idx = tid; idx < 66 * DROW; idx += 256) {
        int row = idx / DROW;
        int col = idx - row * DROW;
        int hh = row - 1, ww = col - 1;
        bool ok = (hh >= 0 && hh < 64 && ww >= 0 && ww < 64);
        sy[idx] = ok ? y1p[hh * 64 + ww] : __float2bfloat16(0.f);
        sx[idx] = ok ? xp[hh * 64 + ww] : __float2bfloat16(0.f);
    }
    if (tid < 81) {
        bf16 h = __float2bfloat16(ws2[c * 81 + tid]);
        taps2[tid] = __nv_bfloat162(h, h);
    }
    if (tid < 9) {
        bf16 h = __float2bfloat16(bs2[c * 9 + tid]);
        tb2[tid] = __nv_bfloat162(h, h);
    }
    __syncthreads();

    float sum = 0.f;
    for (int pp2 = tid; pp2 < 2048; pp2 += 256) {
        const int hq = pp2 >> 5;
        const int c0 = (pp2 & 31) * 2;
        const int w0i = c0 >> 1;

        __nv_bfloat162 yp[9], xpr[9];
#pragma unroll
        for (int di = 0; di < 3; di++) {
            const uint32_t* ry = (const uint32_t*)(sy + (hq + di) * DROW);
            const uint32_t* rx = (const uint32_t*)(sx + (hq + di) * DROW);
            uint32_t ya = ry[w0i], yb = ry[w0i + 1];
            uint32_t xa = rx[w0i], xb = rx[w0i + 1];
            yp[di * 3 + 0] = u2bf2(ya);
            yp[di * 3 + 1] = u2bf2((ya >> 16) | (yb << 16));
            yp[di * 3 + 2] = u2bf2(yb);
            xpr[di * 3 + 0] = u2bf2(xa);
            xpr[di * 3 + 1] = u2bf2((xa >> 16) | (xb << 16));
            xpr[di * 3 + 2] = u2bf2(xb);
        }

        __nv_bfloat162 o = __nv_bfloat162(__float2bfloat16(0.f), __float2bfloat16(0.f));
#pragma unroll
        for (int kk = 0; kk < 9; kk++) {
            __nv_bfloat162 ks = tb2[kk];
#pragma unroll
            for (int r = 0; r < 9; r++)
                ks = __hfma2(yp[r], taps2[kk * 9 + r], ks);
            o = __hfma2(xpr[kk], ks, o);
        }

        int p0 = hq * 64 + c0;
        *(__nv_bfloat162*)(&Out[((size_t)b * CH + c) * HWP + p0]) = o;
        sum += __bfloat162float(o.x) + __bfloat162float(o.y);
    }
    red[tid] = sum;
    __syncthreads();
    for (int s = 128; s > 0; s >>= 1) {
        if (tid < s) red[tid] += red[tid + s];
        __syncthreads();
    }
    if (tid == 0) Mean[b * CH + c] = red[0] * (1.f / HWP);
}

// ============================================================
// SE gate (one block per batch element)
// ============================================================
__global__ __launch_bounds__(192) void se_kernel(
    const float* __restrict__ Mean,
    const float* __restrict__ wc0, const float* __restrict__ bc0,
    const float* __restrict__ wc1, const float* __restrict__ bc1,
    float* __restrict__ Gate)
{
    __shared__ float m[CH];
    __shared__ float hbuf[CH];
    const int b = blockIdx.x;
    const int i = threadIdx.x;
    m[i] = Mean[b * CH + i];
    __syncthreads();
    float s = bc0[i];
    const float* w = wc0 + (size_t)i * CH;
#pragma unroll 8
    for (int j = 0; j < CH; j++) s = fmaf(w[j], m[j], s);
    hbuf[i] = s > 0.f ? s : 0.1f * s;
    __syncthreads();
    float s2 = bc1[i];
    const float* w2 = wc1 + (size_t)i * CH;
#pragma unroll 8
    for (int j = 0; j < CH; j++) s2 = fmaf(w2[j], hbuf[j], s2);
    Gate[b * CH + i] = 1.f / (1.f + expf(-s2));
}

extern "C" void kernel_launch(void* const* d_in, const int* in_sizes, int n_in,
                              void* d_out, int out_size)
{
    const float* input = (const float*)d_in[0];
    const float* lc    = (const float*)d_in[1];
    const int*   mask  = (const int*)d_in[2];
    const float* w0  = (const float*)d_in[3];
    const float* b0  = (const float*)d_in[4];
    const float* w1  = (const float*)d_in[5];
    const float* b1  = (const float*)d_in[6];
    const float* ws0 = (const float*)d_in[7];
    const float* bs0 = (const float*)d_in[8];
    const float* ws1 = (const float*)d_in[9];
    const float* bs1 = (const float*)d_in[10];
    const float* ws2 = (const float*)d_in[11];
    const float* bs2 = (const float*)d_in[12];
    const float* wc0 = (const float*)d_in[13];
    const float* bc0 = (const float*)d_in[14];
    const float* wc1 = (const float*)d_in[15];
    const float* bc1 = (const float*)d_in[16];
    const float* wo  = (const float*)d_in[17];
    const float* bo  = (const float*)d_in[18];
    float* out = (float*)d_out;

    bf16 *pb0, *pb1, *pb2, *pb3, *pw0b, *pw1b, *pwsxb, *pwob, *pwrb;
    float *pT, *pMean, *pGate;
    cudaGetSymbolAddress((void**)&pb0, g_b0);
    cudaGetSymbolAddress((void**)&pb1, g_b1);
    cudaGetSymbolAddress((void**)&pb2, g_b2);
    cudaGetSymbolAddress((void**)&pb3, g_b3);
    cudaGetSymbolAddress((void**)&pw0b, g_w0b);
    cudaGetSymbolAddress((void**)&pw1b, g_w1b);
    cudaGetSymbolAddress((void**)&pwsxb, g_wsxb);
    cudaGetSymbolAddress((void**)&pwob, g_wob);
    cudaGetSymbolAddress((void**)&pwrb, g_wrb);
    cudaGetSymbolAddress((void**)&pT, g_T);
    cudaGetSymbolAddress((void**)&pMean, g_mean);
    cudaGetSymbolAddress((void**)&pGate, g_gate);

    const int conv_smem  = 2 * 13824 * 2 + 2 * PSTAGEW * 4;        // 83,456 B
    const int chain_smem = (2 * BBUF + APAN) * 2;                  // 228,352 B
    cudaFuncSetAttribute(conv3x3_tc,
                         cudaFuncAttributeMaxDynamicSharedMemorySize, conv_smem);
    cudaFuncSetAttribute(chain3_tc,
                         cudaFuncAttributeMaxDynamicSharedMemorySize, chain_smem);

    // 0) prep weights + T table (merged)
    prep_all<<<NPREP + BSZ * MASKN * 6, 256>>>(
        w0, w1, ws0, ws1, wo, lc, pw0b, pw1b, pwsxb, pwob, pwrb, pT);
    // 1) fused chain: v -> x -> y0  (x to g_b1, y0 interleaved to g_b2)
    chain3_tc<<<dim3(16, 1, 8), 512, chain_smem>>>(
        input, pw0b, pw1b, pwsxb, b0, b1, bs0, mask, pT, pb1, pb2);
    // 2) y1 = lrelu(conv3x3(y0, ws1, bs1))
    conv3x3_tc<<<dim3(16, 3, 8), 128, conv_smem>>>(pb2, pwrb, bs1, pb3);
    // 3) out_feat = dynamic_conv(x, depthwise(y1)) ; per-(b,c) mean
    dyn_kernel<<<dim3(CH, BSZ), 256>>>(pb3, pb1, ws2, bs2, pb0, pMean);
    // 4) gate
    se_kernel<<<BSZ, 192>>>(pMean, wc0, bc0, wc1, bc1, pGate);
    // 5) out = conv1x1(gate*out_feat, wo, bo) + input
    gemm_final_tc<<<dim3(16, 3, 8), 256>>>(
        pb0, pwob, bo, out, pGate, input);
}